// round 1
// baseline (speedup 1.0000x reference)
#include <cuda_runtime.h>

#define LL 4096
#define EE 512
#define HH 8
#define DD 64
#define BBATCH 2
#define MROWS (BBATCH*LL)      // 8192
#define BHD (BBATCH*HH)        // 16

// Scratch (static device arrays: allocation-free rule)
__device__ float g_qr[BHD*LL*DD];
__device__ float g_qi[BHD*LL*DD];
__device__ float g_kr[BHD*LL*DD];
__device__ float g_ki[BHD*LL*DD];
__device__ float g_vr[BHD*LL*DD];
__device__ float g_o [BBATCH*LL*EE];

// ---------------------------------------------------------------------------
// C[M,N] = A[M,K] @ W[N,K]^T + bias   (M=8192, N=K=512)
// BM=128, BN=64, BK=16, 256 threads, 8x4 per-thread tile.
// HEAD=true: write C into [B,H,L,D] head-major layout (BN==D so coalesced).
// ---------------------------------------------------------------------------
template<bool HEAD>
__global__ void __launch_bounds__(256)
gemm_nt_kernel(const float* __restrict__ A, const float* __restrict__ Wm,
               const float* __restrict__ bias, float* __restrict__ C)
{
    __shared__ float As[16][128];
    __shared__ float Bs[16][64];
    const int tid  = threadIdx.x;
    const int ty   = tid >> 4, tx = tid & 15;
    const int row0 = blockIdx.y << 7;
    const int col0 = blockIdx.x << 6;

    float acc[8][4];
#pragma unroll
    for (int i = 0; i < 8; i++)
#pragma unroll
        for (int j = 0; j < 4; j++) acc[i][j] = 0.f;

    for (int k0 = 0; k0 < EE; k0 += 16) {
#pragma unroll
        for (int i = 0; i < 2; i++) {
            int f = tid + i * 256;
            int m = f >> 2, kv = f & 3;
            const float4 v = *(const float4*)(A + (size_t)(row0 + m) * EE + k0 + kv * 4);
            As[kv*4+0][m] = v.x; As[kv*4+1][m] = v.y;
            As[kv*4+2][m] = v.z; As[kv*4+3][m] = v.w;
        }
        {
            int n = tid >> 2, kv = tid & 3;
            const float4 v = *(const float4*)(Wm + (size_t)(col0 + n) * EE + k0 + kv * 4);
            Bs[kv*4+0][n] = v.x; Bs[kv*4+1][n] = v.y;
            Bs[kv*4+2][n] = v.z; Bs[kv*4+3][n] = v.w;
        }
        __syncthreads();
#pragma unroll
        for (int k = 0; k < 16; k++) {
            float4 a0 = *(const float4*)&As[k][ty*8];
            float4 a1 = *(const float4*)&As[k][ty*8+4];
            float4 b  = *(const float4*)&Bs[k][tx*4];
            float av[8] = {a0.x,a0.y,a0.z,a0.w,a1.x,a1.y,a1.z,a1.w};
            float bv[4] = {b.x,b.y,b.z,b.w};
#pragma unroll
            for (int i = 0; i < 8; i++)
#pragma unroll
                for (int j = 0; j < 4; j++)
                    acc[i][j] += av[i] * bv[j];
        }
        __syncthreads();
    }

    float4 bb = *(const float4*)(bias + col0 + tx*4);
    float bvv[4] = {bb.x, bb.y, bb.z, bb.w};
#pragma unroll
    for (int i = 0; i < 8; i++) {
        int m = row0 + ty*8 + i;
        float4 ov;
        ov.x = acc[i][0] + bvv[0];
        ov.y = acc[i][1] + bvv[1];
        ov.z = acc[i][2] + bvv[2];
        ov.w = acc[i][3] + bvv[3];
        if (HEAD) {
            int b_ = m >> 12;          // m / L
            int l  = m & (LL - 1);
            int h  = col0 >> 6;        // BN==D==64
            *(float4*)(C + ((size_t)((b_*HH + h)*LL + l)) * DD + tx*4) = ov;
        } else {
            *(float4*)(C + (size_t)m * EE + col0 + tx*4) = ov;
        }
    }
}

// ---------------------------------------------------------------------------
// Flash attention, complex scores: S = (qr kr^T + qi ki^T)/8, mask j <= i-129,
// online softmax, O = P vr, written directly into [B,L,E].
// Block: 64 queries x one (b,h). 256 threads, 16x16 grid, 4x4 register tiles.
// ---------------------------------------------------------------------------
#define SP 68
#define ATTN_SMEM (6*64*SP*4)

__global__ void __launch_bounds__(256)
attn_kernel(const float* __restrict__ qr, const float* __restrict__ qi,
            const float* __restrict__ kr, const float* __restrict__ ki,
            const float* __restrict__ vr, float* __restrict__ o)
{
    extern __shared__ float sm[];
    float* sQr = sm;
    float* sQi = sQr + 64*SP;
    float* sKr = sQi + 64*SP;
    float* sKi = sKr + 64*SP;
    float* sV  = sKi + 64*SP;
    float* sP  = sV  + 64*SP;

    const int qt = blockIdx.x;
    const int bh = blockIdx.y;
    const int b  = bh >> 3;
    const int h  = bh & 7;
    const int tid = threadIdx.x;
    const int ty = tid >> 4, tx = tid & 15;
    const int r0 = ty*4, c0 = tx*4;
    const size_t base = (size_t)bh * LL * DD;

    // Q tiles, transposed [d][r]
    for (int e = tid; e < 4096; e += 256) {
        int r = e >> 6, d = e & 63;
        size_t g = base + (size_t)(qt*64 + r) * DD + d;
        sQr[d*SP + r] = qr[g];
        sQi[d*SP + r] = qi[g];
    }

    float m_[4], l_[4], acc[4][4];
#pragma unroll
    for (int i = 0; i < 4; i++) {
        m_[i] = -1e30f; l_[i] = 0.f;
#pragma unroll
        for (int j = 0; j < 4; j++) acc[i][j] = 0.f;
    }

    const int jt0 = (qt >= 2) ? (qt - 2) : 0;
    for (int jt = jt0; jt < LL/64; jt++) {
        __syncthreads();   // covers Q load (1st iter) + sK/sV/sP reuse (later)
        for (int e = tid; e < 4096; e += 256) {
            int r = e >> 6, d = e & 63;
            size_t g = base + (size_t)(jt*64 + r) * DD + d;
            sKr[d*SP + r] = kr[g];
            sKi[d*SP + r] = ki[g];
            sV [r*SP + d] = vr[g];
        }
        __syncthreads();

        float s[4][4];
#pragma unroll
        for (int i = 0; i < 4; i++)
#pragma unroll
            for (int j = 0; j < 4; j++) s[i][j] = 0.f;

#pragma unroll 16
        for (int d = 0; d < 64; d++) {
            float4 ar4 = *(const float4*)&sQr[d*SP + r0];
            float4 ai4 = *(const float4*)&sQi[d*SP + r0];
            float4 br4 = *(const float4*)&sKr[d*SP + c0];
            float4 bi4 = *(const float4*)&sKi[d*SP + c0];
            float arr[4] = {ar4.x, ar4.y, ar4.z, ar4.w};
            float aii[4] = {ai4.x, ai4.y, ai4.z, ai4.w};
            float brr[4] = {br4.x, br4.y, br4.z, br4.w};
            float bii[4] = {bi4.x, bi4.y, bi4.z, bi4.w};
#pragma unroll
            for (int i = 0; i < 4; i++)
#pragma unroll
                for (int j = 0; j < 4; j++)
                    s[i][j] += arr[i]*brr[j] + aii[i]*bii[j];
        }

#pragma unroll
        for (int i = 0; i < 4; i++)
#pragma unroll
            for (int j = 0; j < 4; j++) s[i][j] *= 0.125f;

        if (jt == qt - 2) {   // only tile that can be partially masked
#pragma unroll
            for (int i = 0; i < 4; i++)
#pragma unroll
                for (int j = 0; j < 4; j++)
                    if ((qt*64 + r0 + i) - (jt*64 + c0 + j) >= 129)
                        s[i][j] = -1e30f;
        }

        // row max across this thread then across 16 tx lanes
        float tm[4];
#pragma unroll
        for (int i = 0; i < 4; i++)
            tm[i] = fmaxf(fmaxf(s[i][0], s[i][1]), fmaxf(s[i][2], s[i][3]));
#pragma unroll
        for (int off = 8; off; off >>= 1)
#pragma unroll
            for (int i = 0; i < 4; i++)
                tm[i] = fmaxf(tm[i], __shfl_xor_sync(0xffffffffu, tm[i], off));

        float corr[4];
#pragma unroll
        for (int i = 0; i < 4; i++) {
            float nm = fmaxf(m_[i], tm[i]);
            corr[i] = __expf(m_[i] - nm);
            m_[i] = nm;
        }

        float p[4][4], rs[4];
#pragma unroll
        for (int i = 0; i < 4; i++) {
            rs[i] = 0.f;
#pragma unroll
            for (int j = 0; j < 4; j++) {
                p[i][j] = __expf(s[i][j] - m_[i]);
                rs[i] += p[i][j];
            }
        }
#pragma unroll
        for (int off = 8; off; off >>= 1)
#pragma unroll
            for (int i = 0; i < 4; i++)
                rs[i] += __shfl_xor_sync(0xffffffffu, rs[i], off);

#pragma unroll
        for (int i = 0; i < 4; i++) {
            l_[i] = l_[i] * corr[i] + rs[i];
#pragma unroll
            for (int j = 0; j < 4; j++) acc[i][j] *= corr[i];
        }

#pragma unroll
        for (int i = 0; i < 4; i++)
            *(float4*)&sP[(r0 + i)*SP + c0] =
                make_float4(p[i][0], p[i][1], p[i][2], p[i][3]);
        __syncthreads();

#pragma unroll 16
        for (int kk = 0; kk < 64; kk++) {
            float4 v4 = *(const float4*)&sV[kk*SP + c0];
            float vv[4] = {v4.x, v4.y, v4.z, v4.w};
            float pk[4];
#pragma unroll
            for (int i = 0; i < 4; i++) pk[i] = sP[(r0 + i)*SP + kk];
#pragma unroll
            for (int i = 0; i < 4; i++)
#pragma unroll
                for (int j = 0; j < 4; j++)
                    acc[i][j] += pk[i] * vv[j];
        }
    }

#pragma unroll
    for (int i = 0; i < 4; i++) {
        float inv = 1.0f / l_[i];
        int lg = qt*64 + r0 + i;
        float4 ov = make_float4(acc[i][0]*inv, acc[i][1]*inv,
                                acc[i][2]*inv, acc[i][3]*inv);
        *(float4*)(o + ((size_t)(b*LL + lg)) * EE + h*DD + c0) = ov;
    }
}

// ---------------------------------------------------------------------------
extern "C" void kernel_launch(void* const* d_in, const int* in_sizes, int n_in,
                              void* d_out, int out_size)
{
    (void)in_sizes; (void)n_in; (void)out_size;
    const float* query = (const float*)d_in[0];
    const float* key_  = (const float*)d_in[1];
    const float* value = (const float*)d_in[2];
    const float* qWr = (const float*)d_in[3];
    const float* qWi = (const float*)d_in[4];
    const float* qbr = (const float*)d_in[5];
    const float* qbi = (const float*)d_in[6];
    const float* kWr = (const float*)d_in[7];
    const float* kWi = (const float*)d_in[8];
    const float* kbr = (const float*)d_in[9];
    const float* kbi = (const float*)d_in[10];
    const float* vWr = (const float*)d_in[11];
    const float* vbr = (const float*)d_in[13];
    // d_in[12] (vWi), d_in[14] (vbi) intentionally unused: Im(V) is discarded.
    const float* oWr = (const float*)d_in[15];
    const float* oWi = (const float*)d_in[16];
    const float* obr = (const float*)d_in[17];
    const float* obi = (const float*)d_in[18];
    float* out = (float*)d_out;

    float *p_qr, *p_qi, *p_kr, *p_ki, *p_vr, *p_o;
    cudaGetSymbolAddress((void**)&p_qr, g_qr);
    cudaGetSymbolAddress((void**)&p_qi, g_qi);
    cudaGetSymbolAddress((void**)&p_kr, g_kr);
    cudaGetSymbolAddress((void**)&p_ki, g_ki);
    cudaGetSymbolAddress((void**)&p_vr, g_vr);
    cudaGetSymbolAddress((void**)&p_o,  g_o);

    cudaFuncSetAttribute(attn_kernel,
                         cudaFuncAttributeMaxDynamicSharedMemorySize, ATTN_SMEM);

    dim3 ggrid(EE/64, MROWS/128);   // (8, 64)

    gemm_nt_kernel<true><<<ggrid, 256>>>(query, qWr, qbr, p_qr);
    gemm_nt_kernel<true><<<ggrid, 256>>>(query, qWi, qbi, p_qi);
    gemm_nt_kernel<true><<<ggrid, 256>>>(key_,  kWr, kbr, p_kr);
    gemm_nt_kernel<true><<<ggrid, 256>>>(key_,  kWi, kbi, p_ki);
    gemm_nt_kernel<true><<<ggrid, 256>>>(value, vWr, vbr, p_vr);

    attn_kernel<<<dim3(LL/64, BHD), 256, ATTN_SMEM>>>(p_qr, p_qi, p_kr, p_ki,
                                                      p_vr, p_o);

    gemm_nt_kernel<false><<<ggrid, 256>>>(p_o, oWr, obr, out);
    gemm_nt_kernel<false><<<ggrid, 256>>>(p_o, oWi, obi, out + (size_t)MROWS*EE);
}

// round 2
// speedup vs baseline: 2.8733x; 2.8733x over previous
#include <cuda_runtime.h>
#include <cstdint>

#define LL 4096
#define EE 512
#define HH 8
#define DD 64
#define BBATCH 2
#define MROWS (BBATCH*LL)      // 8192
#define BHD (BBATCH*HH)        // 16

// Scratch (static device arrays: allocation-free rule)
__device__ float g_qr[BHD*LL*DD];
__device__ float g_qi[BHD*LL*DD];
__device__ float g_kr[BHD*LL*DD];
__device__ float g_ki[BHD*LL*DD];
__device__ float g_vr[BHD*LL*DD];
__device__ float g_o [BBATCH*LL*EE];

// ---------------------------------------------------------------------------
// tf32 helpers
// ---------------------------------------------------------------------------
__device__ __forceinline__ uint32_t f2tf(float x) {
    uint32_t r;
    asm("cvt.rna.tf32.f32 %0, %1;" : "=r"(r) : "f"(x));
    return r;
}
__device__ __forceinline__ float f2tff(float x) {
    return __uint_as_float(f2tf(x));
}
__device__ __forceinline__ void mma8(float* c,
    uint32_t a0, uint32_t a1, uint32_t a2, uint32_t a3,
    uint32_t b0, uint32_t b1)
{
    asm volatile(
        "mma.sync.aligned.m16n8k8.row.col.f32.tf32.tf32.f32 "
        "{%0,%1,%2,%3}, {%4,%5,%6,%7}, {%8,%9}, {%0,%1,%2,%3};"
        : "+f"(c[0]), "+f"(c[1]), "+f"(c[2]), "+f"(c[3])
        : "r"(a0), "r"(a1), "r"(a2), "r"(a3), "r"(b0), "r"(b1));
}
__device__ __forceinline__ void cp16(uint32_t s, const void* g) {
    asm volatile("cp.async.cg.shared.global [%0], [%1], 16;" :: "r"(s), "l"(g));
}

// ---------------------------------------------------------------------------
// GEMM: C[M,N] = A[M,K] @ W[N,K]^T + bias, M=8192, N=K=512
// BM=128, BN=64, BK=32, 128 threads (4 warps, each 64x32), tf32 mma,
// cp.async double buffer. HEAD=true writes [B,H,L,D] layout.
// ---------------------------------------------------------------------------
#define GS 36
#define GEMM_SMEM ((2*128*GS + 2*64*GS) * 4)

template<bool HEAD>
__global__ void __launch_bounds__(128)
gemm_tc(const float* __restrict__ A, const float* __restrict__ W,
        const float* __restrict__ bias, float* __restrict__ C)
{
    extern __shared__ float smg[];
    float* As = smg;               // [2][128*GS]
    float* Bs = smg + 2*128*GS;    // [2][64*GS]

    const int tid  = threadIdx.x;
    const int lane = tid & 31, warp = tid >> 5;
    const int row0 = blockIdx.y << 7;
    const int col0 = blockIdx.x << 6;
    const int wm0  = (warp >> 1) << 6;   // 0 / 64
    const int wn0  = (warp & 1) << 5;    // 0 / 32

    float acc[4][4][4];
#pragma unroll
    for (int mi = 0; mi < 4; mi++)
#pragma unroll
        for (int ni = 0; ni < 4; ni++)
#pragma unroll
            for (int cc = 0; cc < 4; cc++) acc[mi][ni][cc] = 0.f;

    // tile loader: K-tile t into buffer buf
    auto load_tile = [&](int t, int buf) {
        const int k0 = t << 5;
        float* a = As + buf * 128 * GS;
        float* b = Bs + buf * 64 * GS;
#pragma unroll
        for (int i = 0; i < 8; i++) {
            int idx = tid + (i << 7);
            int m = idx >> 3, kv = idx & 7;
            cp16((uint32_t)__cvta_generic_to_shared(a + m * GS + (kv << 2)),
                 A + (size_t)(row0 + m) * EE + k0 + (kv << 2));
        }
#pragma unroll
        for (int i = 0; i < 4; i++) {
            int idx = tid + (i << 7);
            int n = idx >> 3, kv = idx & 7;
            cp16((uint32_t)__cvta_generic_to_shared(b + n * GS + (kv << 2)),
                 W + (size_t)(col0 + n) * EE + k0 + (kv << 2));
        }
        asm volatile("cp.async.commit_group;");
    };

    load_tile(0, 0);
    load_tile(1, 1);

    for (int t = 0; t < 16; t++) {
        asm volatile("cp.async.wait_group 1;");
        __syncthreads();
        const float* a = As + (t & 1) * 128 * GS;
        const float* b = Bs + (t & 1) * 64 * GS;
#pragma unroll
        for (int kk = 0; kk < 4; kk++) {
            uint32_t af[4][4], bf[4][2];
            const int c = (kk << 3) + (lane & 3);
#pragma unroll
            for (int mi = 0; mi < 4; mi++) {
                int r = wm0 + (mi << 4) + (lane >> 2);
                af[mi][0] = f2tf(a[r * GS + c]);
                af[mi][1] = f2tf(a[(r + 8) * GS + c]);
                af[mi][2] = f2tf(a[r * GS + c + 4]);
                af[mi][3] = f2tf(a[(r + 8) * GS + c + 4]);
            }
#pragma unroll
            for (int ni = 0; ni < 4; ni++) {
                int n = wn0 + (ni << 3) + (lane >> 2);
                bf[ni][0] = f2tf(b[n * GS + c]);
                bf[ni][1] = f2tf(b[n * GS + c + 4]);
            }
#pragma unroll
            for (int mi = 0; mi < 4; mi++)
#pragma unroll
                for (int ni = 0; ni < 4; ni++)
                    mma8(acc[mi][ni], af[mi][0], af[mi][1], af[mi][2], af[mi][3],
                         bf[ni][0], bf[ni][1]);
        }
        __syncthreads();
        if (t + 2 < 16) load_tile(t + 2, t & 1);
        else            asm volatile("cp.async.commit_group;");
    }

    // epilogue
#pragma unroll
    for (int mi = 0; mi < 4; mi++) {
#pragma unroll
        for (int ni = 0; ni < 4; ni++) {
            int r  = row0 + wm0 + (mi << 4) + (lane >> 2);
            int cL = wn0 + (ni << 3) + ((lane & 3) << 1);
            float b0 = bias[col0 + cL], b1 = bias[col0 + cL + 1];
            float2 v0 = make_float2(acc[mi][ni][0] + b0, acc[mi][ni][1] + b1);
            float2 v1 = make_float2(acc[mi][ni][2] + b0, acc[mi][ni][3] + b1);
            if (HEAD) {
                int b_ = r >> 12, l = r & (LL - 1);
                int h  = col0 >> 6;
                size_t o = ((size_t)((b_ * HH + h) * LL + l)) * DD + cL;
                *(float2*)(C + o)            = v0;
                *(float2*)(C + o + 8 * DD)   = v1;   // row r+8
            } else {
                *(float2*)(C + (size_t)r * EE + col0 + cL)        = v0;
                *(float2*)(C + (size_t)(r + 8) * EE + col0 + cL)  = v1;
            }
        }
    }
}

// ---------------------------------------------------------------------------
// Flash attention with tf32 mma.
// Block: 64 queries x one (b,h), 128 threads = 4 warps.
// Warp w owns query rows [w*16, w*16+16) against all 64 keys of each tile.
// S = (Qr Kr^T + Qi Ki^T)/8, band mask i-j>=129 only on tile jt==qt-2,
// online softmax (4-lane shfl), P->smem (warp-private rows), PV via mma.
// ---------------------------------------------------------------------------
#define AP 68
#define ATTN_SMEM (5*64*AP*4)

__global__ void __launch_bounds__(128)
attn_tc(const float* __restrict__ qr, const float* __restrict__ qi,
        const float* __restrict__ kr, const float* __restrict__ ki,
        const float* __restrict__ vr, float* __restrict__ o)
{
    extern __shared__ float sm[];
    float* sKr = sm;
    float* sKi = sm + 64 * AP;
    float* sV  = sm + 2 * 64 * AP;
    float* sQr = sm + 3 * 64 * AP;   // reused as sP after Q-frag extraction
    float* sQi = sm + 4 * 64 * AP;
    float* sP  = sQr;

    const int tid = threadIdx.x, lane = tid & 31, warp = tid >> 5;
    const int qt = blockIdx.x, bh = blockIdx.y;
    const size_t base = (size_t)bh * LL * DD;
    const int wq0 = warp << 4;

    // ---- prologue: load + convert Q tiles, extract A-fragments to regs ----
    {
        const float* gqr = qr + base + (size_t)qt * 64 * DD;
        const float* gqi = qi + base + (size_t)qt * 64 * DD;
#pragma unroll
        for (int i = 0; i < 8; i++) {
            int idx = tid + (i << 7);
            int r = idx >> 4, c4 = (idx & 15) << 2;
            float4 v = *(const float4*)(gqr + r * DD + c4);
            sQr[r * AP + c4 + 0] = f2tff(v.x);
            sQr[r * AP + c4 + 1] = f2tff(v.y);
            sQr[r * AP + c4 + 2] = f2tff(v.z);
            sQr[r * AP + c4 + 3] = f2tff(v.w);
            float4 w = *(const float4*)(gqi + r * DD + c4);
            sQi[r * AP + c4 + 0] = f2tff(w.x);
            sQi[r * AP + c4 + 1] = f2tff(w.y);
            sQi[r * AP + c4 + 2] = f2tff(w.z);
            sQi[r * AP + c4 + 3] = f2tff(w.w);
        }
    }
    __syncthreads();

    uint32_t aQr[8][4], aQi[8][4];
#pragma unroll
    for (int kk = 0; kk < 8; kk++) {
        int r = wq0 + (lane >> 2);
        int c = (kk << 3) + (lane & 3);
        aQr[kk][0] = __float_as_uint(sQr[r * AP + c]);
        aQr[kk][1] = __float_as_uint(sQr[(r + 8) * AP + c]);
        aQr[kk][2] = __float_as_uint(sQr[r * AP + c + 4]);
        aQr[kk][3] = __float_as_uint(sQr[(r + 8) * AP + c + 4]);
        aQi[kk][0] = __float_as_uint(sQi[r * AP + c]);
        aQi[kk][1] = __float_as_uint(sQi[(r + 8) * AP + c]);
        aQi[kk][2] = __float_as_uint(sQi[r * AP + c + 4]);
        aQi[kk][3] = __float_as_uint(sQi[(r + 8) * AP + c + 4]);
    }
    // Each warp read only its own 16 rows of sQr; those rows are only ever
    // rewritten (as sP) by the same warp -> no extra block sync needed.

    float m_[2] = {-1e30f, -1e30f}, l_[2] = {0.f, 0.f};
    float oAcc[8][4];
#pragma unroll
    for (int ni = 0; ni < 8; ni++)
#pragma unroll
        for (int cc = 0; cc < 4; cc++) oAcc[ni][cc] = 0.f;

    const int jt0 = (qt >= 2) ? (qt - 2) : 0;
    for (int jt = jt0; jt < LL / 64; jt++) {
        __syncthreads();   // all warps done reading previous K/V
        {
            const float* gkr = kr + base + (size_t)jt * 64 * DD;
            const float* gki = ki + base + (size_t)jt * 64 * DD;
            const float* gv  = vr + base + (size_t)jt * 64 * DD;
#pragma unroll
            for (int i = 0; i < 8; i++) {
                int idx = tid + (i << 7);
                int r = idx >> 4, c4 = (idx & 15) << 2;
                float4 a = *(const float4*)(gkr + r * DD + c4);
                sKr[r * AP + c4 + 0] = f2tff(a.x);
                sKr[r * AP + c4 + 1] = f2tff(a.y);
                sKr[r * AP + c4 + 2] = f2tff(a.z);
                sKr[r * AP + c4 + 3] = f2tff(a.w);
                float4 b = *(const float4*)(gki + r * DD + c4);
                sKi[r * AP + c4 + 0] = f2tff(b.x);
                sKi[r * AP + c4 + 1] = f2tff(b.y);
                sKi[r * AP + c4 + 2] = f2tff(b.z);
                sKi[r * AP + c4 + 3] = f2tff(b.w);
                float4 c = *(const float4*)(gv + r * DD + c4);
                sV[r * AP + c4 + 0] = f2tff(c.x);
                sV[r * AP + c4 + 1] = f2tff(c.y);
                sV[r * AP + c4 + 2] = f2tff(c.z);
                sV[r * AP + c4 + 3] = f2tff(c.w);
            }
        }
        __syncthreads();

        // ---- scores: S = Qr Kr^T + Qi Ki^T ----
        float s[8][4];
#pragma unroll
        for (int ni = 0; ni < 8; ni++)
#pragma unroll
            for (int cc = 0; cc < 4; cc++) s[ni][cc] = 0.f;

#pragma unroll
        for (int kk = 0; kk < 8; kk++) {
            const int c = (kk << 3) + (lane & 3);
            const int nr = lane >> 2;
#pragma unroll
            for (int ni = 0; ni < 8; ni++) {
                int n = (ni << 3) + nr;
                uint32_t br0 = __float_as_uint(sKr[n * AP + c]);
                uint32_t br1 = __float_as_uint(sKr[n * AP + c + 4]);
                uint32_t bi0 = __float_as_uint(sKi[n * AP + c]);
                uint32_t bi1 = __float_as_uint(sKi[n * AP + c + 4]);
                mma8(s[ni], aQr[kk][0], aQr[kk][1], aQr[kk][2], aQr[kk][3], br0, br1);
                mma8(s[ni], aQi[kk][0], aQi[kk][1], aQi[kk][2], aQi[kk][3], bi0, bi1);
            }
        }

#pragma unroll
        for (int ni = 0; ni < 8; ni++)
#pragma unroll
            for (int cc = 0; cc < 4; cc++) s[ni][cc] *= 0.125f;

        if (jt == qt - 2) {   // only tile where the band mask can bite
            int ig0 = qt * 64 + wq0 + (lane >> 2);
            int jg  = jt * 64 + ((lane & 3) << 1);
#pragma unroll
            for (int ni = 0; ni < 8; ni++) {
                int j0 = jg + (ni << 3);
                if (ig0 - j0       >= 129) s[ni][0] = -1e30f;
                if (ig0 - j0 - 1   >= 129) s[ni][1] = -1e30f;
                if (ig0 + 8 - j0   >= 129) s[ni][2] = -1e30f;
                if (ig0 + 7 - j0   >= 129) s[ni][3] = -1e30f;
            }
        }

        // ---- online softmax (rows: lane>>2 and +8; 4-lane groups own rows) --
        float mx0 = -1e30f, mx1 = -1e30f;
#pragma unroll
        for (int ni = 0; ni < 8; ni++) {
            mx0 = fmaxf(mx0, fmaxf(s[ni][0], s[ni][1]));
            mx1 = fmaxf(mx1, fmaxf(s[ni][2], s[ni][3]));
        }
        mx0 = fmaxf(mx0, __shfl_xor_sync(0xffffffffu, mx0, 1));
        mx0 = fmaxf(mx0, __shfl_xor_sync(0xffffffffu, mx0, 2));
        mx1 = fmaxf(mx1, __shfl_xor_sync(0xffffffffu, mx1, 1));
        mx1 = fmaxf(mx1, __shfl_xor_sync(0xffffffffu, mx1, 2));

        float nm0 = fmaxf(m_[0], mx0), nm1 = fmaxf(m_[1], mx1);
        float corr0 = __expf(m_[0] - nm0), corr1 = __expf(m_[1] - nm1);
        m_[0] = nm0; m_[1] = nm1;

        float rs0 = 0.f, rs1 = 0.f;
#pragma unroll
        for (int ni = 0; ni < 8; ni++) {
            s[ni][0] = __expf(s[ni][0] - nm0); rs0 += s[ni][0];
            s[ni][1] = __expf(s[ni][1] - nm0); rs0 += s[ni][1];
            s[ni][2] = __expf(s[ni][2] - nm1); rs1 += s[ni][2];
            s[ni][3] = __expf(s[ni][3] - nm1); rs1 += s[ni][3];
        }
        rs0 += __shfl_xor_sync(0xffffffffu, rs0, 1);
        rs0 += __shfl_xor_sync(0xffffffffu, rs0, 2);
        rs1 += __shfl_xor_sync(0xffffffffu, rs1, 1);
        rs1 += __shfl_xor_sync(0xffffffffu, rs1, 2);

        l_[0] = l_[0] * corr0 + rs0;
        l_[1] = l_[1] * corr1 + rs1;
#pragma unroll
        for (int ni = 0; ni < 8; ni++) {
            oAcc[ni][0] *= corr0; oAcc[ni][1] *= corr0;
            oAcc[ni][2] *= corr1; oAcc[ni][3] *= corr1;
        }

        // ---- P -> smem (warp-private rows), then PV mma ----
        {
            int r = wq0 + (lane >> 2);
            int c = (lane & 3) << 1;
#pragma unroll
            for (int ni = 0; ni < 8; ni++) {
                float2 p0 = make_float2(f2tff(s[ni][0]), f2tff(s[ni][1]));
                float2 p1 = make_float2(f2tff(s[ni][2]), f2tff(s[ni][3]));
                *(float2*)&sP[r * AP + (ni << 3) + c]       = p0;
                *(float2*)&sP[(r + 8) * AP + (ni << 3) + c] = p1;
            }
        }
        __syncwarp();

#pragma unroll
        for (int kk = 0; kk < 8; kk++) {
            int r = wq0 + (lane >> 2);
            int c = (kk << 3) + (lane & 3);
            uint32_t a0 = __float_as_uint(sP[r * AP + c]);
            uint32_t a1 = __float_as_uint(sP[(r + 8) * AP + c]);
            uint32_t a2 = __float_as_uint(sP[r * AP + c + 4]);
            uint32_t a3 = __float_as_uint(sP[(r + 8) * AP + c + 4]);
#pragma unroll
            for (int ni = 0; ni < 8; ni++) {
                int n = (ni << 3) + (lane >> 2);
                uint32_t b0 = __float_as_uint(sV[c * AP + n]);
                uint32_t b1 = __float_as_uint(sV[(c + 4) * AP + n]);
                mma8(oAcc[ni], a0, a1, a2, a3, b0, b1);
            }
        }
    }

    // ---- epilogue: normalize, write [B,L,E] ----
    float inv0 = 1.f / l_[0], inv1 = 1.f / l_[1];
    int b_ = bh >> 3, h = bh & 7;
    int r  = qt * 64 + wq0 + (lane >> 2);
    int c  = (lane & 3) << 1;
#pragma unroll
    for (int ni = 0; ni < 8; ni++) {
        int d = (ni << 3) + c;
        float2 v0 = make_float2(oAcc[ni][0] * inv0, oAcc[ni][1] * inv0);
        float2 v1 = make_float2(oAcc[ni][2] * inv1, oAcc[ni][3] * inv1);
        *(float2*)(o + ((size_t)(b_ * LL + r)) * EE + h * DD + d)     = v0;
        *(float2*)(o + ((size_t)(b_ * LL + r + 8)) * EE + h * DD + d) = v1;
    }
}

// ---------------------------------------------------------------------------
extern "C" void kernel_launch(void* const* d_in, const int* in_sizes, int n_in,
                              void* d_out, int out_size)
{
    (void)in_sizes; (void)n_in; (void)out_size;
    const float* query = (const float*)d_in[0];
    const float* key_  = (const float*)d_in[1];
    const float* value = (const float*)d_in[2];
    const float* qWr = (const float*)d_in[3];
    const float* qWi = (const float*)d_in[4];
    const float* qbr = (const float*)d_in[5];
    const float* qbi = (const float*)d_in[6];
    const float* kWr = (const float*)d_in[7];
    const float* kWi = (const float*)d_in[8];
    const float* kbr = (const float*)d_in[9];
    const float* kbi = (const float*)d_in[10];
    const float* vWr = (const float*)d_in[11];
    const float* vbr = (const float*)d_in[13];
    // d_in[12] (vWi), d_in[14] (vbi) unused: Im(V) is discarded by reference.
    const float* oWr = (const float*)d_in[15];
    const float* oWi = (const float*)d_in[16];
    const float* obr = (const float*)d_in[17];
    const float* obi = (const float*)d_in[18];
    float* out = (float*)d_out;

    float *p_qr, *p_qi, *p_kr, *p_ki, *p_vr, *p_o;
    cudaGetSymbolAddress((void**)&p_qr, g_qr);
    cudaGetSymbolAddress((void**)&p_qi, g_qi);
    cudaGetSymbolAddress((void**)&p_kr, g_kr);
    cudaGetSymbolAddress((void**)&p_ki, g_ki);
    cudaGetSymbolAddress((void**)&p_vr, g_vr);
    cudaGetSymbolAddress((void**)&p_o,  g_o);

    cudaFuncSetAttribute(gemm_tc<true>,
                         cudaFuncAttributeMaxDynamicSharedMemorySize, GEMM_SMEM);
    cudaFuncSetAttribute(gemm_tc<false>,
                         cudaFuncAttributeMaxDynamicSharedMemorySize, GEMM_SMEM);
    cudaFuncSetAttribute(attn_tc,
                         cudaFuncAttributeMaxDynamicSharedMemorySize, ATTN_SMEM);

    dim3 ggrid(EE / 64, MROWS / 128);   // (8, 64)

    gemm_tc<true><<<ggrid, 128, GEMM_SMEM>>>(query, qWr, qbr, p_qr);
    gemm_tc<true><<<ggrid, 128, GEMM_SMEM>>>(query, qWi, qbi, p_qi);
    gemm_tc<true><<<ggrid, 128, GEMM_SMEM>>>(key_,  kWr, kbr, p_kr);
    gemm_tc<true><<<ggrid, 128, GEMM_SMEM>>>(key_,  kWi, kbi, p_ki);
    gemm_tc<true><<<ggrid, 128, GEMM_SMEM>>>(value, vWr, vbr, p_vr);

    attn_tc<<<dim3(LL / 64, BHD), 128, ATTN_SMEM>>>(p_qr, p_qi, p_kr, p_ki,
                                                    p_vr, p_o);

    gemm_tc<false><<<ggrid, 128, GEMM_SMEM>>>(p_o, oWr, obr, out);
    gemm_tc<false><<<ggrid, 128, GEMM_SMEM>>>(p_o, oWi, obi,
                                              out + (size_t)MROWS * EE);
}

// round 3
// speedup vs baseline: 3.6246x; 1.2615x over previous
#include <cuda_runtime.h>
#include <cstdint>

#define LL 4096
#define EE 512
#define HH 8
#define DD 64
#define BBATCH 2
#define MROWS (BBATCH*LL)      // 8192
#define BHD (BBATCH*HH)        // 16

// Scratch (static device arrays: allocation-free rule)
__device__ float g_qr[BHD*LL*DD];
__device__ float g_qi[BHD*LL*DD];
__device__ float g_kr[BHD*LL*DD];
__device__ float g_ki[BHD*LL*DD];
__device__ float g_vr[BHD*LL*DD];
__device__ float g_o [BBATCH*LL*EE];

// ---------------------------------------------------------------------------
// helpers
// ---------------------------------------------------------------------------
__device__ __forceinline__ uint32_t f2tf(float x) {
    uint32_t r;
    asm("cvt.rna.tf32.f32 %0, %1;" : "=r"(r) : "f"(x));
    return r;
}
__device__ __forceinline__ float f2tff(float x) {
    return __uint_as_float(f2tf(x));
}
__device__ __forceinline__ void mma8(float* c, const uint32_t* a,
                                     uint32_t b0, uint32_t b1)
{
    asm volatile(
        "mma.sync.aligned.m16n8k8.row.col.f32.tf32.tf32.f32 "
        "{%0,%1,%2,%3}, {%4,%5,%6,%7}, {%8,%9}, {%0,%1,%2,%3};"
        : "+f"(c[0]), "+f"(c[1]), "+f"(c[2]), "+f"(c[3])
        : "r"(a[0]), "r"(a[1]), "r"(a[2]), "r"(a[3]), "r"(b0), "r"(b1));
}
__device__ __forceinline__ void cp16(uint32_t s, const void* g) {
    asm volatile("cp.async.cg.shared.global [%0], [%1], 16;" :: "r"(s), "l"(g));
}
__device__ __forceinline__ void ldsm4(uint32_t* r, uint32_t a) {
    asm volatile("ldmatrix.sync.aligned.m8n8.x4.shared.b16 {%0,%1,%2,%3}, [%4];"
        : "=r"(r[0]), "=r"(r[1]), "=r"(r[2]), "=r"(r[3]) : "r"(a));
}
__device__ __forceinline__ uint32_t s2u(const void* p) {
    return (uint32_t)__cvta_generic_to_shared(p);
}

// ---------------------------------------------------------------------------
// GEMM: C[M,N] = A[M,K] @ W[N,K]^T + bias, M=8192, N=K=512.
// BM=128, BN=128, BK=32, 256 threads (8 warps, 64x32 warp tiles), tf32 mma,
// ldmatrix fragment loads, 2-stage cp.async ring.
// ---------------------------------------------------------------------------
#define GKS 36
#define GSTAGE (2*128*GKS)            // floats per stage (A then B)
#define GEMM_SMEM (2*GSTAGE*4)        // 73728 B

template<bool HEAD>
__global__ void __launch_bounds__(256, 2)
gemm_tc(const float* __restrict__ A, const float* __restrict__ W,
        const float* __restrict__ bias, float* __restrict__ C)
{
    extern __shared__ float smg[];
    const int tid  = threadIdx.x;
    const int lane = tid & 31, warp = tid >> 5;
    const int row0 = blockIdx.y << 7;
    const int col0 = blockIdx.x << 7;
    const int wm = (warp >> 2) << 6;     // 0/64
    const int wn = (warp & 3) << 5;      // 0/32/64/96

    const int g  = lane >> 3, rr = lane & 7;
    const int ar = (g & 1) * 8 + rr, ac = (g >> 1) * 4;   // A-frag lane addr
    const int br = (g >> 1) * 8 + rr, bc = (g & 1) * 4;   // B-pair lane addr

    float acc[4][4][4];
#pragma unroll
    for (int mi = 0; mi < 4; mi++)
#pragma unroll
        for (int ni = 0; ni < 4; ni++)
#pragma unroll
            for (int cc = 0; cc < 4; cc++) acc[mi][ni][cc] = 0.f;

    auto load_tile = [&](int t, int buf) {
        const int k0 = t << 5;
        float* a = smg + buf * GSTAGE;
        float* b = a + 128 * GKS;
#pragma unroll
        for (int i = 0; i < 4; i++) {
            int idx = tid + (i << 8);
            int m = idx >> 3, kv = idx & 7;
            cp16(s2u(a + m * GKS + (kv << 2)),
                 A + (size_t)(row0 + m) * EE + k0 + (kv << 2));
        }
#pragma unroll
        for (int i = 0; i < 4; i++) {
            int idx = tid + (i << 8);
            int n = idx >> 3, kv = idx & 7;
            cp16(s2u(b + n * GKS + (kv << 2)),
                 W + (size_t)(col0 + n) * EE + k0 + (kv << 2));
        }
        asm volatile("cp.async.commit_group;");
    };

    load_tile(0, 0);

    for (int t = 0; t < 16; t++) {
        asm volatile("cp.async.wait_group 0;");
        __syncthreads();
        if (t + 1 < 16) load_tile(t + 1, (t + 1) & 1);

        const float* a = smg + (t & 1) * GSTAGE;
        const float* b = a + 128 * GKS;
#pragma unroll
        for (int kk = 0; kk < 4; kk++) {
            uint32_t af[4][4], bf[2][4];
#pragma unroll
            for (int mi = 0; mi < 4; mi++) {
                ldsm4(af[mi], s2u(a + (wm + mi * 16 + ar) * GKS + kk * 8 + ac));
#pragma unroll
                for (int j = 0; j < 4; j++)
                    af[mi][j] = f2tf(__uint_as_float(af[mi][j]));
            }
#pragma unroll
            for (int np = 0; np < 2; np++) {
                ldsm4(bf[np], s2u(b + (wn + np * 16 + br) * GKS + kk * 8 + bc));
#pragma unroll
                for (int j = 0; j < 4; j++)
                    bf[np][j] = f2tf(__uint_as_float(bf[np][j]));
            }
#pragma unroll
            for (int mi = 0; mi < 4; mi++)
#pragma unroll
                for (int np = 0; np < 2; np++) {
                    mma8(acc[mi][2*np],   af[mi], bf[np][0], bf[np][1]);
                    mma8(acc[mi][2*np+1], af[mi], bf[np][2], bf[np][3]);
                }
        }
        __syncthreads();
    }

    // epilogue
#pragma unroll
    for (int mi = 0; mi < 4; mi++) {
#pragma unroll
        for (int ni = 0; ni < 4; ni++) {
            int r  = row0 + wm + mi * 16 + (lane >> 2);
            int cL = col0 + wn + ni * 8 + ((lane & 3) << 1);
            float b0 = bias[cL], b1 = bias[cL + 1];
            float2 v0 = make_float2(acc[mi][ni][0] + b0, acc[mi][ni][1] + b1);
            float2 v1 = make_float2(acc[mi][ni][2] + b0, acc[mi][ni][3] + b1);
            if (HEAD) {
                int b_ = r >> 12, l = r & (LL - 1);
                int h  = cL >> 6, d = cL & 63;
                size_t o = ((size_t)((b_ * HH + h) * LL + l)) * DD + d;
                *(float2*)(C + o)          = v0;
                *(float2*)(C + o + 8 * DD) = v1;
            } else {
                *(float2*)(C + (size_t)r * EE + cL)       = v0;
                *(float2*)(C + (size_t)(r + 8) * EE + cL) = v1;
            }
        }
    }
}

// ---------------------------------------------------------------------------
// Flash attention, tf32 mma + ldmatrix. 128 queries per block, 8 warps.
// Warp w owns rows [w*16, w*16+16). S = (Qr Kr^T + Qi Ki^T)/8,
// band mask i-j>=129, online softmax, O = P vr -> [B,L,E].
// ---------------------------------------------------------------------------
#define AP 68
#define SKR 0
#define SKI (64*AP)
#define SV  (128*AP)
#define SPP (192*AP)
#define ATTN_SMEM (320*AP*4)    // 87040 B

__global__ void __launch_bounds__(256, 1)
attn_tc(const float* __restrict__ qr, const float* __restrict__ qi,
        const float* __restrict__ kr, const float* __restrict__ ki,
        const float* __restrict__ vr, float* __restrict__ o)
{
    extern __shared__ float sm[];
    const int tid = threadIdx.x, lane = tid & 31, warp = tid >> 5;
    const int q0 = blockIdx.x << 7;
    const int bh = blockIdx.y;
    const size_t base = (size_t)bh * LL * DD;
    const int wq0 = warp << 4;

    const int g  = lane >> 3, rr = lane & 7;
    const int ar = (g & 1) * 8 + rr, ac = (g >> 1) * 4;   // A-frag
    const int br = (g >> 1) * 8 + rr, bc = (g & 1) * 4;   // B-pair

    // ---- stage Q (Qr->sP region, Qi->sKr region), extract A-frags ----
    {
        const float* gqr = qr + base + (size_t)q0 * DD;
        const float* gqi = qi + base + (size_t)q0 * DD;
#pragma unroll
        for (int i = 0; i < 8; i++) {
            int idx = tid + (i << 8);
            int r = idx >> 4, c4 = (idx & 15) << 2;
            float4 v = *(const float4*)(gqr + r * DD + c4);
            sm[SPP + r * AP + c4 + 0] = f2tff(v.x);
            sm[SPP + r * AP + c4 + 1] = f2tff(v.y);
            sm[SPP + r * AP + c4 + 2] = f2tff(v.z);
            sm[SPP + r * AP + c4 + 3] = f2tff(v.w);
            float4 w = *(const float4*)(gqi + r * DD + c4);
            sm[SKR + r * AP + c4 + 0] = f2tff(w.x);
            sm[SKR + r * AP + c4 + 1] = f2tff(w.y);
            sm[SKR + r * AP + c4 + 2] = f2tff(w.z);
            sm[SKR + r * AP + c4 + 3] = f2tff(w.w);
        }
    }
    __syncthreads();

    uint32_t aQr[8][4], aQi[8][4];
#pragma unroll
    for (int kk = 0; kk < 8; kk++) {
        ldsm4(aQr[kk], s2u(sm + SPP + (wq0 + ar) * AP + kk * 8 + ac));
        ldsm4(aQi[kk], s2u(sm + SKR + (wq0 + ar) * AP + kk * 8 + ac));
    }

    float m_[2] = {-1e30f, -1e30f}, l_[2] = {0.f, 0.f};
    float oAcc[8][4];
#pragma unroll
    for (int ni = 0; ni < 8; ni++)
#pragma unroll
        for (int cc = 0; cc < 4; cc++) oAcc[ni][cc] = 0.f;

    const int jt0 = (blockIdx.x >= 1) ? (2 * blockIdx.x - 2) : 0;
    for (int jt = jt0; jt < LL / 64; jt++) {
        __syncthreads();
        {
            const float* gkr = kr + base + (size_t)jt * 64 * DD;
            const float* gki = ki + base + (size_t)jt * 64 * DD;
#pragma unroll
            for (int i = 0; i < 4; i++) {
                int idx = tid + (i << 8);
                int r = idx >> 4, c4 = (idx & 15) << 2;
                float4 a = *(const float4*)(gkr + r * DD + c4);
                sm[SKR + r * AP + c4 + 0] = f2tff(a.x);
                sm[SKR + r * AP + c4 + 1] = f2tff(a.y);
                sm[SKR + r * AP + c4 + 2] = f2tff(a.z);
                sm[SKR + r * AP + c4 + 3] = f2tff(a.w);
                float4 b = *(const float4*)(gki + r * DD + c4);
                sm[SKI + r * AP + c4 + 0] = f2tff(b.x);
                sm[SKI + r * AP + c4 + 1] = f2tff(b.y);
                sm[SKI + r * AP + c4 + 2] = f2tff(b.z);
                sm[SKI + r * AP + c4 + 3] = f2tff(b.w);
            }
            // V transposed: sV[d][key], coalesced LDG + 4x4 reg transpose
            const float* gv = vr + base + (size_t)jt * 64 * DD;
            int db = (tid & 15) << 2, kb = (tid >> 4) << 2;
            float4 v0 = *(const float4*)(gv + (kb + 0) * DD + db);
            float4 v1 = *(const float4*)(gv + (kb + 1) * DD + db);
            float4 v2 = *(const float4*)(gv + (kb + 2) * DD + db);
            float4 v3 = *(const float4*)(gv + (kb + 3) * DD + db);
            *(float4*)&sm[SV + (db + 0) * AP + kb] =
                make_float4(f2tff(v0.x), f2tff(v1.x), f2tff(v2.x), f2tff(v3.x));
            *(float4*)&sm[SV + (db + 1) * AP + kb] =
                make_float4(f2tff(v0.y), f2tff(v1.y), f2tff(v2.y), f2tff(v3.y));
            *(float4*)&sm[SV + (db + 2) * AP + kb] =
                make_float4(f2tff(v0.z), f2tff(v1.z), f2tff(v2.z), f2tff(v3.z));
            *(float4*)&sm[SV + (db + 3) * AP + kb] =
                make_float4(f2tff(v0.w), f2tff(v1.w), f2tff(v2.w), f2tff(v3.w));
        }
        __syncthreads();

        // warp fully below the band for this tile? skip
        if (q0 + wq0 >= jt * 64 + 192) continue;

        // ---- scores ----
        float s[8][4];
#pragma unroll
        for (int ni = 0; ni < 8; ni++)
#pragma unroll
            for (int cc = 0; cc < 4; cc++) s[ni][cc] = 0.f;

#pragma unroll
        for (int kk = 0; kk < 8; kk++) {
#pragma unroll
            for (int np = 0; np < 4; np++) {
                uint32_t bkr[4], bki[4];
                ldsm4(bkr, s2u(sm + SKR + (np * 16 + br) * AP + kk * 8 + bc));
                ldsm4(bki, s2u(sm + SKI + (np * 16 + br) * AP + kk * 8 + bc));
                mma8(s[2*np],   aQr[kk], bkr[0], bkr[1]);
                mma8(s[2*np+1], aQr[kk], bkr[2], bkr[3]);
                mma8(s[2*np],   aQi[kk], bki[0], bki[1]);
                mma8(s[2*np+1], aQi[kk], bki[2], bki[3]);
            }
        }

#pragma unroll
        for (int ni = 0; ni < 8; ni++)
#pragma unroll
            for (int cc = 0; cc < 4; cc++) s[ni][cc] *= 0.125f;

        if (q0 + wq0 + 15 >= jt * 64 + 129) {   // band mask can bite this warp
            int ig0 = q0 + wq0 + (lane >> 2);
            int jg  = jt * 64 + ((lane & 3) << 1);
#pragma unroll
            for (int ni = 0; ni < 8; ni++) {
                int j0 = jg + (ni << 3);
                if (ig0 - j0     >= 129) s[ni][0] = -1e30f;
                if (ig0 - j0 - 1 >= 129) s[ni][1] = -1e30f;
                if (ig0 + 8 - j0 >= 129) s[ni][2] = -1e30f;
                if (ig0 + 7 - j0 >= 129) s[ni][3] = -1e30f;
            }
        }

        // ---- online softmax ----
        float mx0 = -1e30f, mx1 = -1e30f;
#pragma unroll
        for (int ni = 0; ni < 8; ni++) {
            mx0 = fmaxf(mx0, fmaxf(s[ni][0], s[ni][1]));
            mx1 = fmaxf(mx1, fmaxf(s[ni][2], s[ni][3]));
        }
        mx0 = fmaxf(mx0, __shfl_xor_sync(0xffffffffu, mx0, 1));
        mx0 = fmaxf(mx0, __shfl_xor_sync(0xffffffffu, mx0, 2));
        mx1 = fmaxf(mx1, __shfl_xor_sync(0xffffffffu, mx1, 1));
        mx1 = fmaxf(mx1, __shfl_xor_sync(0xffffffffu, mx1, 2));

        float nm0 = fmaxf(m_[0], mx0), nm1 = fmaxf(m_[1], mx1);
        float corr0 = __expf(m_[0] - nm0), corr1 = __expf(m_[1] - nm1);
        m_[0] = nm0; m_[1] = nm1;

        float rs0 = 0.f, rs1 = 0.f;
#pragma unroll
        for (int ni = 0; ni < 8; ni++) {
            s[ni][0] = __expf(s[ni][0] - nm0); rs0 += s[ni][0];
            s[ni][1] = __expf(s[ni][1] - nm0); rs0 += s[ni][1];
            s[ni][2] = __expf(s[ni][2] - nm1); rs1 += s[ni][2];
            s[ni][3] = __expf(s[ni][3] - nm1); rs1 += s[ni][3];
        }
        rs0 += __shfl_xor_sync(0xffffffffu, rs0, 1);
        rs0 += __shfl_xor_sync(0xffffffffu, rs0, 2);
        rs1 += __shfl_xor_sync(0xffffffffu, rs1, 1);
        rs1 += __shfl_xor_sync(0xffffffffu, rs1, 2);

        l_[0] = l_[0] * corr0 + rs0;
        l_[1] = l_[1] * corr1 + rs1;
#pragma unroll
        for (int ni = 0; ni < 8; ni++) {
            oAcc[ni][0] *= corr0; oAcc[ni][1] *= corr0;
            oAcc[ni][2] *= corr1; oAcc[ni][3] *= corr1;
        }

        // ---- P -> smem (warp-private rows), PV via ldmatrix + mma ----
        {
            int r = wq0 + (lane >> 2);
            int c = (lane & 3) << 1;
#pragma unroll
            for (int ni = 0; ni < 8; ni++) {
                *(float2*)&sm[SPP + r * AP + (ni << 3) + c] =
                    make_float2(f2tff(s[ni][0]), f2tff(s[ni][1]));
                *(float2*)&sm[SPP + (r + 8) * AP + (ni << 3) + c] =
                    make_float2(f2tff(s[ni][2]), f2tff(s[ni][3]));
            }
        }
        __syncwarp();

#pragma unroll
        for (int kk = 0; kk < 8; kk++) {
            uint32_t pa[4];
            ldsm4(pa, s2u(sm + SPP + (wq0 + ar) * AP + kk * 8 + ac));
#pragma unroll
            for (int dp = 0; dp < 4; dp++) {
                uint32_t bv[4];
                ldsm4(bv, s2u(sm + SV + (dp * 16 + br) * AP + kk * 8 + bc));
                mma8(oAcc[2*dp],   pa, bv[0], bv[1]);
                mma8(oAcc[2*dp+1], pa, bv[2], bv[3]);
            }
        }
    }

    // ---- epilogue ----
    float inv0 = 1.f / l_[0], inv1 = 1.f / l_[1];
    int b_ = bh >> 3, h = bh & 7;
    int r  = q0 + wq0 + (lane >> 2);
    int c  = (lane & 3) << 1;
#pragma unroll
    for (int ni = 0; ni < 8; ni++) {
        int d = (ni << 3) + c;
        *(float2*)(o + ((size_t)(b_ * LL + r)) * EE + h * DD + d) =
            make_float2(oAcc[ni][0] * inv0, oAcc[ni][1] * inv0);
        *(float2*)(o + ((size_t)(b_ * LL + r + 8)) * EE + h * DD + d) =
            make_float2(oAcc[ni][2] * inv1, oAcc[ni][3] * inv1);
    }
}

// ---------------------------------------------------------------------------
extern "C" void kernel_launch(void* const* d_in, const int* in_sizes, int n_in,
                              void* d_out, int out_size)
{
    (void)in_sizes; (void)n_in; (void)out_size;
    const float* query = (const float*)d_in[0];
    const float* key_  = (const float*)d_in[1];
    const float* value = (const float*)d_in[2];
    const float* qWr = (const float*)d_in[3];
    const float* qWi = (const float*)d_in[4];
    const float* qbr = (const float*)d_in[5];
    const float* qbi = (const float*)d_in[6];
    const float* kWr = (const float*)d_in[7];
    const float* kWi = (const float*)d_in[8];
    const float* kbr = (const float*)d_in[9];
    const float* kbi = (const float*)d_in[10];
    const float* vWr = (const float*)d_in[11];
    const float* vbr = (const float*)d_in[13];
    // d_in[12] (vWi), d_in[14] (vbi) unused: Im(V) is discarded by reference.
    const float* oWr = (const float*)d_in[15];
    const float* oWi = (const float*)d_in[16];
    const float* obr = (const float*)d_in[17];
    const float* obi = (const float*)d_in[18];
    float* out = (float*)d_out;

    float *p_qr, *p_qi, *p_kr, *p_ki, *p_vr, *p_o;
    cudaGetSymbolAddress((void**)&p_qr, g_qr);
    cudaGetSymbolAddress((void**)&p_qi, g_qi);
    cudaGetSymbolAddress((void**)&p_kr, g_kr);
    cudaGetSymbolAddress((void**)&p_ki, g_ki);
    cudaGetSymbolAddress((void**)&p_vr, g_vr);
    cudaGetSymbolAddress((void**)&p_o,  g_o);

    cudaFuncSetAttribute(gemm_tc<true>,
                         cudaFuncAttributeMaxDynamicSharedMemorySize, GEMM_SMEM);
    cudaFuncSetAttribute(gemm_tc<false>,
                         cudaFuncAttributeMaxDynamicSharedMemorySize, GEMM_SMEM);
    cudaFuncSetAttribute(attn_tc,
                         cudaFuncAttributeMaxDynamicSharedMemorySize, ATTN_SMEM);

    dim3 ggrid(EE / 128, MROWS / 128);   // (4, 64)

    gemm_tc<true><<<ggrid, 256, GEMM_SMEM>>>(query, qWr, qbr, p_qr);
    gemm_tc<true><<<ggrid, 256, GEMM_SMEM>>>(query, qWi, qbi, p_qi);
    gemm_tc<true><<<ggrid, 256, GEMM_SMEM>>>(key_,  kWr, kbr, p_kr);
    gemm_tc<true><<<ggrid, 256, GEMM_SMEM>>>(key_,  kWi, kbi, p_ki);
    gemm_tc<true><<<ggrid, 256, GEMM_SMEM>>>(value, vWr, vbr, p_vr);

    attn_tc<<<dim3(LL / 128, BHD), 256, ATTN_SMEM>>>(p_qr, p_qi, p_kr, p_ki,
                                                     p_vr, p_o);

    gemm_tc<false><<<ggrid, 256, GEMM_SMEM>>>(p_o, oWr, obr, out);
    gemm_tc<false><<<ggrid, 256, GEMM_SMEM>>>(p_o, oWi, obi,
                                              out + (size_t)MROWS * EE);
}

// round 5
// speedup vs baseline: 3.8701x; 1.0677x over previous
#include <cuda_runtime.h>
#include <cstdint>

#define LL 4096
#define EE 512
#define HH 8
#define DD 64
#define BBATCH 2
#define MROWS (BBATCH*LL)      // 8192
#define BHD (BBATCH*HH)        // 16

// Scratch (static device arrays: allocation-free rule)
__device__ float g_qr[BHD*LL*DD];
__device__ float g_qi[BHD*LL*DD];
__device__ float g_kr[BHD*LL*DD];
__device__ float g_ki[BHD*LL*DD];
__device__ float g_vr[BHD*LL*DD];
__device__ float g_o [BBATCH*LL*EE];
// tf32-pre-rounded inputs/weights
__device__ float g_q[MROWS*EE];
__device__ float g_k[MROWS*EE];
__device__ float g_v[MROWS*EE];
__device__ float g_wqr[EE*EE];
__device__ float g_wqi[EE*EE];
__device__ float g_wkr[EE*EE];
__device__ float g_wki[EE*EE];
__device__ float g_wvr[EE*EE];
__device__ float g_wor[EE*EE];
__device__ float g_woi[EE*EE];

// ---------------------------------------------------------------------------
// helpers
// ---------------------------------------------------------------------------
__device__ __forceinline__ uint32_t f2tf(float x) {
    uint32_t r;
    asm("cvt.rna.tf32.f32 %0, %1;" : "=r"(r) : "f"(x));
    return r;
}
__device__ __forceinline__ float f2tff(float x) {
    return __uint_as_float(f2tf(x));
}
__device__ __forceinline__ void mma8(float* c, const uint32_t* a,
                                     uint32_t b0, uint32_t b1)
{
    asm volatile(
        "mma.sync.aligned.m16n8k8.row.col.f32.tf32.tf32.f32 "
        "{%0,%1,%2,%3}, {%4,%5,%6,%7}, {%8,%9}, {%0,%1,%2,%3};"
        : "+f"(c[0]), "+f"(c[1]), "+f"(c[2]), "+f"(c[3])
        : "r"(a[0]), "r"(a[1]), "r"(a[2]), "r"(a[3]), "r"(b0), "r"(b1));
}
__device__ __forceinline__ void cp16(uint32_t s, const void* g) {
    asm volatile("cp.async.cg.shared.global [%0], [%1], 16;" :: "r"(s), "l"(g));
}
__device__ __forceinline__ void ldsm4(uint32_t* r, uint32_t a) {
    asm volatile("ldmatrix.sync.aligned.m8n8.x4.shared.b16 {%0,%1,%2,%3}, [%4];"
        : "=r"(r[0]), "=r"(r[1]), "=r"(r[2]), "=r"(r[3]) : "r"(a));
}
__device__ __forceinline__ uint32_t s2u(const void* p) {
    return (uint32_t)__cvta_generic_to_shared(p);
}

// ---------------------------------------------------------------------------
// Pre-round to tf32 (elementwise, float4). grid.y indexes the job table.
// ---------------------------------------------------------------------------
struct RPair { const float* s; float* d; int n4; };
struct RTab  { RPair t[10]; };

__global__ void __launch_bounds__(256)
round_tf32_k(RTab tab)
{
    RPair p = tab.t[blockIdx.y];
    int stride = gridDim.x * blockDim.x;
    for (int i = blockIdx.x * blockDim.x + threadIdx.x; i < p.n4; i += stride) {
        float4 v = ((const float4*)p.s)[i];
        v.x = f2tff(v.x); v.y = f2tff(v.y);
        v.z = f2tff(v.z); v.w = f2tff(v.w);
        ((float4*)p.d)[i] = v;
    }
}

// ---------------------------------------------------------------------------
// GEMM: C[M,N] = A[M,K] @ W[N,K]^T + bias, M=8192, N=K=512.
// Inputs pre-rounded to tf32 -> no cvt in mainloop. blockIdx.z picks the job.
// BM=BN=128, BK=32, 256 threads, 2-stage cp.async ring, ldmatrix frags.
// HEAD=true: output rounded to tf32 + written in [B,H,L,D] layout.
// ---------------------------------------------------------------------------
struct GJob  { const float* A; const float* W; const float* bias; float* C; };
struct GJobs { GJob j[5]; };

#define GKS 36
#define GSTAGE (2*128*GKS)
#define GEMM_SMEM (2*GSTAGE*4)        // 73728 B

template<bool HEAD>
__global__ void __launch_bounds__(256, 2)
gemm_tc(GJobs jobs)
{
    extern __shared__ float smg[];
    const GJob jb = jobs.j[blockIdx.z];
    const float* __restrict__ A = jb.A;
    const float* __restrict__ W = jb.W;

    const int tid  = threadIdx.x;
    const int lane = tid & 31, warp = tid >> 5;
    const int row0 = blockIdx.y << 7;
    const int col0 = blockIdx.x << 7;
    const int wm = (warp >> 2) << 6;
    const int wn = (warp & 3) << 5;

    const int g  = lane >> 3, rr = lane & 7;
    const int ar = (g & 1) * 8 + rr, ac = (g >> 1) * 4;
    const int br = (g >> 1) * 8 + rr, bc = (g & 1) * 4;

    float acc[4][4][4];
#pragma unroll
    for (int mi = 0; mi < 4; mi++)
#pragma unroll
        for (int ni = 0; ni < 4; ni++)
#pragma unroll
            for (int cc = 0; cc < 4; cc++) acc[mi][ni][cc] = 0.f;

    auto load_tile = [&](int t, int buf) {
        const int k0 = t << 5;
        float* a = smg + buf * GSTAGE;
        float* b = a + 128 * GKS;
#pragma unroll
        for (int i = 0; i < 4; i++) {
            int idx = tid + (i << 8);
            int m = idx >> 3, kv = idx & 7;
            cp16(s2u(a + m * GKS + (kv << 2)),
                 A + (size_t)(row0 + m) * EE + k0 + (kv << 2));
        }
#pragma unroll
        for (int i = 0; i < 4; i++) {
            int idx = tid + (i << 8);
            int n = idx >> 3, kv = idx & 7;
            cp16(s2u(b + n * GKS + (kv << 2)),
                 W + (size_t)(col0 + n) * EE + k0 + (kv << 2));
        }
        asm volatile("cp.async.commit_group;");
    };

    load_tile(0, 0);

    for (int t = 0; t < 16; t++) {
        asm volatile("cp.async.wait_group 0;");
        __syncthreads();
        if (t + 1 < 16) load_tile(t + 1, (t + 1) & 1);

        const float* a = smg + (t & 1) * GSTAGE;
        const float* b = a + 128 * GKS;
#pragma unroll
        for (int kk = 0; kk < 4; kk++) {
            uint32_t af[4][4], bf[2][4];
#pragma unroll
            for (int mi = 0; mi < 4; mi++)
                ldsm4(af[mi], s2u(a + (wm + mi * 16 + ar) * GKS + kk * 8 + ac));
#pragma unroll
            for (int np = 0; np < 2; np++)
                ldsm4(bf[np], s2u(b + (wn + np * 16 + br) * GKS + kk * 8 + bc));
#pragma unroll
            for (int mi = 0; mi < 4; mi++)
#pragma unroll
                for (int np = 0; np < 2; np++) {
                    mma8(acc[mi][2*np],   af[mi], bf[np][0], bf[np][1]);
                    mma8(acc[mi][2*np+1], af[mi], bf[np][2], bf[np][3]);
                }
        }
        __syncthreads();
    }

    // epilogue
#pragma unroll
    for (int mi = 0; mi < 4; mi++) {
#pragma unroll
        for (int ni = 0; ni < 4; ni++) {
            int r  = row0 + wm + mi * 16 + (lane >> 2);
            int cL = col0 + wn + ni * 8 + ((lane & 3) << 1);
            float b0 = jb.bias[cL], b1 = jb.bias[cL + 1];
            float2 v0, v1;
            if (HEAD) {
                v0 = make_float2(f2tff(acc[mi][ni][0] + b0), f2tff(acc[mi][ni][1] + b1));
                v1 = make_float2(f2tff(acc[mi][ni][2] + b0), f2tff(acc[mi][ni][3] + b1));
                int b_ = r >> 12, l = r & (LL - 1);
                int h  = cL >> 6, d = cL & 63;
                size_t o = ((size_t)((b_ * HH + h) * LL + l)) * DD + d;
                *(float2*)(jb.C + o)          = v0;
                *(float2*)(jb.C + o + 8 * DD) = v1;
            } else {
                v0 = make_float2(acc[mi][ni][0] + b0, acc[mi][ni][1] + b1);
                v1 = make_float2(acc[mi][ni][2] + b0, acc[mi][ni][3] + b1);
                *(float2*)(jb.C + (size_t)r * EE + cL)       = v0;
                *(float2*)(jb.C + (size_t)(r + 8) * EE + cL) = v1;
            }
        }
    }
}

// ---------------------------------------------------------------------------
// Flash attention, tf32 mma + ldmatrix, cp.async double-buffered K/Ki/V.
// 128 queries per block, 8 warps; warp w owns rows [w*16, w*16+16).
// All data pre-rounded tf32 -> no cvt except P (after expf).
// ---------------------------------------------------------------------------
#define AP 68
#define TK (64*AP)                 // floats per 64-row tile region
#define SPPOF (6*TK)               // P region: 128*AP floats
#define ATTN_SMEM ((6*64 + 128) * AP * 4)   // 139264 B

__global__ void __launch_bounds__(256)
attn_tc(const float* __restrict__ qr, const float* __restrict__ qi,
        const float* __restrict__ kr, const float* __restrict__ ki,
        const float* __restrict__ vr, float* __restrict__ o)
{
    extern __shared__ float sm[];
    const int tid = threadIdx.x, lane = tid & 31, warp = tid >> 5;
    const int q0 = blockIdx.x << 7;
    const int bh = blockIdx.y;
    const size_t base = (size_t)bh * LL * DD;
    const int wq0 = warp << 4;

    const int g  = lane >> 3, rr = lane & 7;
    const int ar = (g & 1) * 8 + rr, ac = (g >> 1) * 4;
    const int br = (g >> 1) * 8 + rr, bc = (g & 1) * 4;

    // stage one 64-row K/Ki/V tile into buffer at sb (cp.async K/Ki, LDG+STS V^T)
    auto stage_tile = [&](int jt, float* sb) {
        const float* gkr = kr + base + (size_t)jt * 64 * DD;
        const float* gki = ki + base + (size_t)jt * 64 * DD;
#pragma unroll
        for (int i = 0; i < 4; i++) {
            int c = tid + (i << 8);           // 1024 chunks of 16B
            int r = c >> 4, c4 = (c & 15) << 2;
            cp16(s2u(sb + r * AP + c4),      gkr + r * DD + c4);
            cp16(s2u(sb + TK + r * AP + c4), gki + r * DD + c4);
        }
        asm volatile("cp.async.commit_group;");
        const float* gv = vr + base + (size_t)jt * 64 * DD;
        int db = (tid & 15) << 2, kb = (tid >> 4) << 2;
        float4 v0 = *(const float4*)(gv + (kb + 0) * DD + db);
        float4 v1 = *(const float4*)(gv + (kb + 1) * DD + db);
        float4 v2 = *(const float4*)(gv + (kb + 2) * DD + db);
        float4 v3 = *(const float4*)(gv + (kb + 3) * DD + db);
        float* sv = sb + 2 * TK;
        *(float4*)&sv[(db + 0) * AP + kb] = make_float4(v0.x, v1.x, v2.x, v3.x);
        *(float4*)&sv[(db + 1) * AP + kb] = make_float4(v0.y, v1.y, v2.y, v3.y);
        *(float4*)&sv[(db + 2) * AP + kb] = make_float4(v0.z, v1.z, v2.z, v3.z);
        *(float4*)&sv[(db + 3) * AP + kb] = make_float4(v0.w, v1.w, v2.w, v3.w);
    };

    // ---- prologue: Q via cp.async into (buf1, P) regions, extract frags ----
    {
        const float* gqr = qr + base + (size_t)q0 * DD;
        const float* gqi = qi + base + (size_t)q0 * DD;
        float* sQr = sm + 3 * TK;       // buf1 region (overwritten later)
        float* sQi = sm + SPPOF;        // P region
#pragma unroll
        for (int i = 0; i < 8; i++) {
            int c = tid + (i << 8);           // 2048 chunks
            int r = c >> 4, c4 = (c & 15) << 2;
            cp16(s2u(sQr + r * AP + c4), gqr + r * DD + c4);
            cp16(s2u(sQi + r * AP + c4), gqi + r * DD + c4);
        }
        asm volatile("cp.async.commit_group;");
        asm volatile("cp.async.wait_group 0;");
    }
    __syncthreads();

    uint32_t aQr[8][4], aQi[8][4];
#pragma unroll
    for (int kk = 0; kk < 8; kk++) {
        ldsm4(aQr[kk], s2u(sm + 3 * TK + (wq0 + ar) * AP + kk * 8 + ac));
        ldsm4(aQi[kk], s2u(sm + SPPOF  + (wq0 + ar) * AP + kk * 8 + ac));
    }
    __syncthreads();   // frags extracted before buf1/P reused

    float m_[2] = {-1e30f, -1e30f}, l_[2] = {0.f, 0.f};
    float oAcc[8][4];
#pragma unroll
    for (int ni = 0; ni < 8; ni++)
#pragma unroll
        for (int cc = 0; cc < 4; cc++) oAcc[ni][cc] = 0.f;

    const int jt0 = (blockIdx.x >= 1) ? (2 * blockIdx.x - 2) : 0;

    stage_tile(jt0, sm);               // buf0
    asm volatile("cp.async.wait_group 0;");
    __syncthreads();

    for (int jt = jt0; jt < LL / 64; jt++) {
        const int ib = (jt - jt0) & 1;
        const float* cb = sm + ib * 3 * TK;

        if (jt + 1 < LL / 64)
            stage_tile(jt + 1, sm + (ib ^ 1) * 3 * TK);
        else
            asm volatile("cp.async.commit_group;");

        if (q0 + wq0 < jt * 64 + 192) {   // warp has unmasked keys this tile
            const float* sKr = cb;
            const float* sKi = cb + TK;
            const float* sV  = cb + 2 * TK;

            // ---- scores ----
            float s[8][4];
#pragma unroll
            for (int ni = 0; ni < 8; ni++)
#pragma unroll
                for (int cc = 0; cc < 4; cc++) s[ni][cc] = 0.f;

#pragma unroll
            for (int kk = 0; kk < 8; kk++) {
#pragma unroll
                for (int np = 0; np < 4; np++) {
                    uint32_t bkr[4], bki[4];
                    ldsm4(bkr, s2u(sKr + (np * 16 + br) * AP + kk * 8 + bc));
                    ldsm4(bki, s2u(sKi + (np * 16 + br) * AP + kk * 8 + bc));
                    mma8(s[2*np],   aQr[kk], bkr[0], bkr[1]);
                    mma8(s[2*np+1], aQr[kk], bkr[2], bkr[3]);
                    mma8(s[2*np],   aQi[kk], bki[0], bki[1]);
                    mma8(s[2*np+1], aQi[kk], bki[2], bki[3]);
                }
            }

#pragma unroll
            for (int ni = 0; ni < 8; ni++)
#pragma unroll
                for (int cc = 0; cc < 4; cc++) s[ni][cc] *= 0.125f;

            if (q0 + wq0 + 15 >= jt * 64 + 129) {   // band mask can bite
                int ig0 = q0 + wq0 + (lane >> 2);
                int jg  = jt * 64 + ((lane & 3) << 1);
#pragma unroll
                for (int ni = 0; ni < 8; ni++) {
                    int j0 = jg + (ni << 3);
                    if (ig0 - j0     >= 129) s[ni][0] = -1e30f;
                    if (ig0 - j0 - 1 >= 129) s[ni][1] = -1e30f;
                    if (ig0 + 8 - j0 >= 129) s[ni][2] = -1e30f;
                    if (ig0 + 7 - j0 >= 129) s[ni][3] = -1e30f;
                }
            }

            // ---- online softmax ----
            float mx0 = -1e30f, mx1 = -1e30f;
#pragma unroll
            for (int ni = 0; ni < 8; ni++) {
                mx0 = fmaxf(mx0, fmaxf(s[ni][0], s[ni][1]));
                mx1 = fmaxf(mx1, fmaxf(s[ni][2], s[ni][3]));
            }
            mx0 = fmaxf(mx0, __shfl_xor_sync(0xffffffffu, mx0, 1));
            mx0 = fmaxf(mx0, __shfl_xor_sync(0xffffffffu, mx0, 2));
            mx1 = fmaxf(mx1, __shfl_xor_sync(0xffffffffu, mx1, 1));
            mx1 = fmaxf(mx1, __shfl_xor_sync(0xffffffffu, mx1, 2));

            float nm0 = fmaxf(m_[0], mx0), nm1 = fmaxf(m_[1], mx1);
            float corr0 = __expf(m_[0] - nm0), corr1 = __expf(m_[1] - nm1);
            m_[0] = nm0; m_[1] = nm1;

            float rs0 = 0.f, rs1 = 0.f;
#pragma unroll
            for (int ni = 0; ni < 8; ni++) {
                s[ni][0] = __expf(s[ni][0] - nm0); rs0 += s[ni][0];
                s[ni][1] = __expf(s[ni][1] - nm0); rs0 += s[ni][1];
                s[ni][2] = __expf(s[ni][2] - nm1); rs1 += s[ni][2];
                s[ni][3] = __expf(s[ni][3] - nm1); rs1 += s[ni][3];
            }
            rs0 += __shfl_xor_sync(0xffffffffu, rs0, 1);
            rs0 += __shfl_xor_sync(0xffffffffu, rs0, 2);
            rs1 += __shfl_xor_sync(0xffffffffu, rs1, 1);
            rs1 += __shfl_xor_sync(0xffffffffu, rs1, 2);

            l_[0] = l_[0] * corr0 + rs0;
            l_[1] = l_[1] * corr1 + rs1;
#pragma unroll
            for (int ni = 0; ni < 8; ni++) {
                oAcc[ni][0] *= corr0; oAcc[ni][1] *= corr0;
                oAcc[ni][2] *= corr1; oAcc[ni][3] *= corr1;
            }

            // ---- P -> smem (warp-private rows), PV ----
            {
                int r = wq0 + (lane >> 2);
                int c = (lane & 3) << 1;
                float* sP = sm + SPPOF;
#pragma unroll
                for (int ni = 0; ni < 8; ni++) {
                    *(float2*)&sP[r * AP + (ni << 3) + c] =
                        make_float2(f2tff(s[ni][0]), f2tff(s[ni][1]));
                    *(float2*)&sP[(r + 8) * AP + (ni << 3) + c] =
                        make_float2(f2tff(s[ni][2]), f2tff(s[ni][3]));
                }
            }
            __syncwarp();

#pragma unroll
            for (int kk = 0; kk < 8; kk++) {
                uint32_t pa[4];
                ldsm4(pa, s2u(sm + SPPOF + (wq0 + ar) * AP + kk * 8 + ac));
#pragma unroll
                for (int dp = 0; dp < 4; dp++) {
                    uint32_t bv[4];
                    ldsm4(bv, s2u(sV + (dp * 16 + br) * AP + kk * 8 + bc));
                    mma8(oAcc[2*dp],   pa, bv[0], bv[1]);
                    mma8(oAcc[2*dp+1], pa, bv[2], bv[3]);
                }
            }
        }

        asm volatile("cp.async.wait_group 0;");
        __syncthreads();
    }

    // ---- epilogue: normalize, round to tf32, write [B,L,E] ----
    float inv0 = 1.f / l_[0], inv1 = 1.f / l_[1];
    int b_ = bh >> 3, h = bh & 7;
    int r  = q0 + wq0 + (lane >> 2);
    int c  = (lane & 3) << 1;
#pragma unroll
    for (int ni = 0; ni < 8; ni++) {
        int d = (ni << 3) + c;
        *(float2*)(o + ((size_t)(b_ * LL + r)) * EE + h * DD + d) =
            make_float2(f2tff(oAcc[ni][0] * inv0), f2tff(oAcc[ni][1] * inv0));
        *(float2*)(o + ((size_t)(b_ * LL + r + 8)) * EE + h * DD + d) =
            make_float2(f2tff(oAcc[ni][2] * inv1), f2tff(oAcc[ni][3] * inv1));
    }
}

// ---------------------------------------------------------------------------
extern "C" void kernel_launch(void* const* d_in, const int* in_sizes, int n_in,
                              void* d_out, int out_size)
{
    (void)in_sizes; (void)n_in; (void)out_size;
    const float* query = (const float*)d_in[0];
    const float* key_  = (const float*)d_in[1];
    const float* value = (const float*)d_in[2];
    const float* qWr = (const float*)d_in[3];
    const float* qWi = (const float*)d_in[4];
    const float* qbr = (const float*)d_in[5];
    const float* qbi = (const float*)d_in[6];
    const float* kWr = (const float*)d_in[7];
    const float* kWi = (const float*)d_in[8];
    const float* kbr = (const float*)d_in[9];
    const float* kbi = (const float*)d_in[10];
    const float* vWr = (const float*)d_in[11];
    const float* vbr = (const float*)d_in[13];
    // d_in[12] (vWi), d_in[14] (vbi) unused: Im(V) discarded by reference.
    const float* oWr = (const float*)d_in[15];
    const float* oWi = (const float*)d_in[16];
    const float* obr = (const float*)d_in[17];
    const float* obi = (const float*)d_in[18];
    float* out = (float*)d_out;

    float *p_qr, *p_qi, *p_kr, *p_ki, *p_vr, *p_o;
    float *p_q, *p_k, *p_v;
    float *p_wqr, *p_wqi, *p_wkr, *p_wki, *p_wvr, *p_wor, *p_woi;
    cudaGetSymbolAddress((void**)&p_qr, g_qr);
    cudaGetSymbolAddress((void**)&p_qi, g_qi);
    cudaGetSymbolAddress((void**)&p_kr, g_kr);
    cudaGetSymbolAddress((void**)&p_ki, g_ki);
    cudaGetSymbolAddress((void**)&p_vr, g_vr);
    cudaGetSymbolAddress((void**)&p_o,  g_o);
    cudaGetSymbolAddress((void**)&p_q,  g_q);
    cudaGetSymbolAddress((void**)&p_k,  g_k);
    cudaGetSymbolAddress((void**)&p_v,  g_v);
    cudaGetSymbolAddress((void**)&p_wqr, g_wqr);
    cudaGetSymbolAddress((void**)&p_wqi, g_wqi);
    cudaGetSymbolAddress((void**)&p_wkr, g_wkr);
    cudaGetSymbolAddress((void**)&p_wki, g_wki);
    cudaGetSymbolAddress((void**)&p_wvr, g_wvr);
    cudaGetSymbolAddress((void**)&p_wor, g_wor);
    cudaGetSymbolAddress((void**)&p_woi, g_woi);

    cudaFuncSetAttribute(gemm_tc<true>,
                         cudaFuncAttributeMaxDynamicSharedMemorySize, GEMM_SMEM);
    cudaFuncSetAttribute(gemm_tc<false>,
                         cudaFuncAttributeMaxDynamicSharedMemorySize, GEMM_SMEM);
    cudaFuncSetAttribute(attn_tc,
                         cudaFuncAttributeMaxDynamicSharedMemorySize, ATTN_SMEM);

    // ---- pre-round inputs + live weights to tf32 ----
    {
        const int NI4 = MROWS * EE / 4;   // 1,048,576
        const int NW4 = EE * EE / 4;      // 65,536
        RTab rt;
        rt.t[0] = {query, p_q,   NI4};
        rt.t[1] = {key_,  p_k,   NI4};
        rt.t[2] = {value, p_v,   NI4};
        rt.t[3] = {qWr,   p_wqr, NW4};
        rt.t[4] = {qWi,   p_wqi, NW4};
        rt.t[5] = {kWr,   p_wkr, NW4};
        rt.t[6] = {kWi,   p_wki, NW4};
        rt.t[7] = {vWr,   p_wvr, NW4};
        rt.t[8] = {oWr,   p_wor, NW4};
        rt.t[9] = {oWi,   p_woi, NW4};
        round_tf32_k<<<dim3(1024, 10), 256>>>(rt);
    }

    dim3 ggrid5(EE / 128, MROWS / 128, 5);   // (4, 64, 5)
    dim3 ggrid2(EE / 128, MROWS / 128, 2);

    {
        GJobs pj;
        pj.j[0] = {p_q, p_wqr, qbr, p_qr};
        pj.j[1] = {p_q, p_wqi, qbi, p_qi};
        pj.j[2] = {p_k, p_wkr, kbr, p_kr};
        pj.j[3] = {p_k, p_wki, kbi, p_ki};
        pj.j[4] = {p_v, p_wvr, vbr, p_vr};
        gemm_tc<true><<<ggrid5, 256, GEMM_SMEM>>>(pj);
    }

    attn_tc<<<dim3(LL / 128, BHD), 256, ATTN_SMEM>>>(p_qr, p_qi, p_kr, p_ki,
                                                     p_vr, p_o);

    {
        GJobs oj;
        oj.j[0] = {p_o, p_wor, obr, out};
        oj.j[1] = {p_o, p_woi, obi, out + (size_t)MROWS * EE};
        oj.j[2] = oj.j[0]; oj.j[3] = oj.j[0]; oj.j[4] = oj.j[0];
        gemm_tc<false><<<ggrid2, 256, GEMM_SMEM>>>(oj);
    }
}

// round 7
// speedup vs baseline: 4.6544x; 1.2027x over previous
#include <cuda_runtime.h>
#include <cstdint>

#define LL 4096
#define EE 512
#define HH 8
#define DD 64
#define BBATCH 2
#define MROWS (BBATCH*LL)      // 8192
#define BHD (BBATCH*HH)        // 16

// Scratch (static device arrays: allocation-free rule)
__device__ float g_qr[BHD*LL*DD];
__device__ float g_qi[BHD*LL*DD];
__device__ float g_kr[BHD*LL*DD];
__device__ float g_ki[BHD*LL*DD];
__device__ float g_vr[BHD*DD*LL];   // TRANSPOSED: [B,H,D,L]
__device__ float g_o [BBATCH*LL*EE];
// tf32-pre-rounded inputs/weights
__device__ float g_q[MROWS*EE];
__device__ float g_k[MROWS*EE];
__device__ float g_v[MROWS*EE];
__device__ float g_wqr[EE*EE];
__device__ float g_wqi[EE*EE];
__device__ float g_wkr[EE*EE];
__device__ float g_wki[EE*EE];
__device__ float g_wvr[EE*EE];
__device__ float g_wor[EE*EE];
__device__ float g_woi[EE*EE];

// ---------------------------------------------------------------------------
// helpers
// ---------------------------------------------------------------------------
__device__ __forceinline__ uint32_t f2tf(float x) {
    uint32_t r;
    asm("cvt.rna.tf32.f32 %0, %1;" : "=r"(r) : "f"(x));
    return r;
}
__device__ __forceinline__ float f2tff(float x) {
    return __uint_as_float(f2tf(x));
}
__device__ __forceinline__ void mma8(float* c, const uint32_t* a,
                                     uint32_t b0, uint32_t b1)
{
    asm volatile(
        "mma.sync.aligned.m16n8k8.row.col.f32.tf32.tf32.f32 "
        "{%0,%1,%2,%3}, {%4,%5,%6,%7}, {%8,%9}, {%0,%1,%2,%3};"
        : "+f"(c[0]), "+f"(c[1]), "+f"(c[2]), "+f"(c[3])
        : "r"(a[0]), "r"(a[1]), "r"(a[2]), "r"(a[3]), "r"(b0), "r"(b1));
}
__device__ __forceinline__ void cp16(uint32_t s, const void* g) {
    asm volatile("cp.async.cg.shared.global [%0], [%1], 16;" :: "r"(s), "l"(g));
}
__device__ __forceinline__ void ldsm4(uint32_t* r, uint32_t a) {
    asm volatile("ldmatrix.sync.aligned.m8n8.x4.shared.b16 {%0,%1,%2,%3}, [%4];"
        : "=r"(r[0]), "=r"(r[1]), "=r"(r[2]), "=r"(r[3]) : "r"(a));
}
__device__ __forceinline__ uint32_t s2u(const void* p) {
    return (uint32_t)__cvta_generic_to_shared(p);
}

// ---------------------------------------------------------------------------
// Pre-round to tf32 (elementwise, float4). grid.y indexes the job table.
// ---------------------------------------------------------------------------
struct RPair { const float* s; float* d; int n4; };
struct RTab  { RPair t[10]; };

__global__ void __launch_bounds__(256)
round_tf32_k(RTab tab)
{
    RPair p = tab.t[blockIdx.y];
    int stride = gridDim.x * blockDim.x;
    for (int i = blockIdx.x * blockDim.x + threadIdx.x; i < p.n4; i += stride) {
        float4 v = ((const float4*)p.s)[i];
        v.x = f2tff(v.x); v.y = f2tff(v.y);
        v.z = f2tff(v.z); v.w = f2tff(v.w);
        ((float4*)p.d)[i] = v;
    }
}

// ---------------------------------------------------------------------------
// GEMM: C[M,N] = A[M,K] @ W[N,K]^T + bias, M=8192, N=K=512.
// Inputs pre-rounded tf32 -> no cvt in mainloop. blockIdx.z picks the job.
// BM=BN=128, BK=32, 256 threads, 3-stage cp.async ring, ldmatrix frags.
// mode: 0 = flat [M,E] fp32; 1 = head [B,H,L,D] (tf32-rounded);
//       2 = headT [B,H,D,L] (tf32-rounded) for V.
// ---------------------------------------------------------------------------
struct GJob  { const float* A; const float* W; const float* bias; float* C; int mode; };
struct GJobs { GJob j[5]; };

#define GKS 36
#define GSTAGE (2*128*GKS)            // floats per stage
#define GEMM_SMEM (3*GSTAGE*4)        // 110592 B

__global__ void __launch_bounds__(256, 2)
gemm_tc(GJobs jobs)
{
    extern __shared__ float smg[];
    const GJob jb = jobs.j[blockIdx.z];
    const float* __restrict__ A = jb.A;
    const float* __restrict__ W = jb.W;

    const int tid  = threadIdx.x;
    const int lane = tid & 31, warp = tid >> 5;
    const int row0 = blockIdx.y << 7;
    const int col0 = blockIdx.x << 7;
    const int wm = (warp >> 2) << 6;
    const int wn = (warp & 3) << 5;

    const int g  = lane >> 3, rr = lane & 7;
    const int ar = (g & 1) * 8 + rr, ac = (g >> 1) * 4;
    const int br = (g >> 1) * 8 + rr, bc = (g & 1) * 4;

    float acc[4][4][4];
#pragma unroll
    for (int mi = 0; mi < 4; mi++)
#pragma unroll
        for (int ni = 0; ni < 4; ni++)
#pragma unroll
            for (int cc = 0; cc < 4; cc++) acc[mi][ni][cc] = 0.f;

    auto load_tile = [&](int t, int buf) {
        const int k0 = t << 5;
        float* a = smg + buf * GSTAGE;
        float* b = a + 128 * GKS;
#pragma unroll
        for (int i = 0; i < 4; i++) {
            int idx = tid + (i << 8);
            int m = idx >> 3, kv = idx & 7;
            cp16(s2u(a + m * GKS + (kv << 2)),
                 A + (size_t)(row0 + m) * EE + k0 + (kv << 2));
        }
#pragma unroll
        for (int i = 0; i < 4; i++) {
            int idx = tid + (i << 8);
            int n = idx >> 3, kv = idx & 7;
            cp16(s2u(b + n * GKS + (kv << 2)),
                 W + (size_t)(col0 + n) * EE + k0 + (kv << 2));
        }
        asm volatile("cp.async.commit_group;");
    };

    load_tile(0, 0);
    load_tile(1, 1);

    int buf = 0;
    for (int t = 0; t < 16; t++) {
        asm volatile("cp.async.wait_group 1;");   // tile t resident
        __syncthreads();
        if (t + 2 < 16) load_tile(t + 2, (t + 2) % 3);
        else            asm volatile("cp.async.commit_group;");

        const float* a = smg + buf * GSTAGE;
        const float* b = a + 128 * GKS;
#pragma unroll
        for (int kk = 0; kk < 4; kk++) {
            uint32_t af[4][4], bf[2][4];
#pragma unroll
            for (int mi = 0; mi < 4; mi++)
                ldsm4(af[mi], s2u(a + (wm + mi * 16 + ar) * GKS + kk * 8 + ac));
#pragma unroll
            for (int np = 0; np < 2; np++)
                ldsm4(bf[np], s2u(b + (wn + np * 16 + br) * GKS + kk * 8 + bc));
#pragma unroll
            for (int mi = 0; mi < 4; mi++)
#pragma unroll
                for (int np = 0; np < 2; np++) {
                    mma8(acc[mi][2*np],   af[mi], bf[np][0], bf[np][1]);
                    mma8(acc[mi][2*np+1], af[mi], bf[np][2], bf[np][3]);
                }
        }
        buf = (buf + 1) % 3;
    }

    // epilogue
#pragma unroll
    for (int mi = 0; mi < 4; mi++) {
#pragma unroll
        for (int ni = 0; ni < 4; ni++) {
            int r  = row0 + wm + mi * 16 + (lane >> 2);
            int cL = col0 + wn + ni * 8 + ((lane & 3) << 1);
            float b0 = jb.bias[cL], b1 = jb.bias[cL + 1];
            float a0 = acc[mi][ni][0] + b0, a1 = acc[mi][ni][1] + b1;
            float a2 = acc[mi][ni][2] + b0, a3 = acc[mi][ni][3] + b1;
            int b_ = r >> 12, l = r & (LL - 1);
            int h  = cL >> 6, d = cL & 63;
            if (jb.mode == 0) {
                *(float2*)(jb.C + (size_t)r * EE + cL)       = make_float2(a0, a1);
                *(float2*)(jb.C + (size_t)(r + 8) * EE + cL) = make_float2(a2, a3);
            } else if (jb.mode == 1) {
                size_t o = ((size_t)((b_ * HH + h) * LL + l)) * DD + d;
                *(float2*)(jb.C + o)          = make_float2(f2tff(a0), f2tff(a1));
                *(float2*)(jb.C + o + 8 * DD) = make_float2(f2tff(a2), f2tff(a3));
            } else {
                // headT [B,H,D,L]
                size_t o = ((size_t)((b_ * HH + h) * DD + d)) * LL + l;
                jb.C[o]           = f2tff(a0);
                jb.C[o + LL]      = f2tff(a1);
                jb.C[o + 8]       = f2tff(a2);
                jb.C[o + LL + 8]  = f2tff(a3);
            }
        }
    }
}

// ---------------------------------------------------------------------------
// Flash attention, tf32 mma + ldmatrix, all-cp.async double-buffered K/Ki/V.
// 128 queries per block, 8 warps; warp w owns rows [w*16, w*16+16).
// grid = (bh, qx): heavy (low-qx) blocks launch first.
// V read from transposed [B,H,D,L] layout -> no LDG/STS transpose.
// ---------------------------------------------------------------------------
#define AP 68
#define TK (64*AP)
#define SPPOF (6*TK)
#define ATTN_SMEM ((6*64 + 128) * AP * 4)   // 139264 B

__global__ void __launch_bounds__(256)
attn_tc(const float* __restrict__ qr, const float* __restrict__ qi,
        const float* __restrict__ kr, const float* __restrict__ ki,
        const float* __restrict__ vr, float* __restrict__ o)
{
    extern __shared__ float sm[];
    const int tid = threadIdx.x, lane = tid & 31, warp = tid >> 5;
    const int bh = blockIdx.x;
    const int qx = blockIdx.y;
    const int q0 = qx << 7;
    const size_t base  = (size_t)bh * LL * DD;
    const size_t baseT = (size_t)bh * DD * LL;
    const int wq0 = warp << 4;

    const int g  = lane >> 3, rr = lane & 7;
    const int ar = (g & 1) * 8 + rr, ac = (g >> 1) * 4;
    const int br = (g >> 1) * 8 + rr, bc = (g & 1) * 4;

    // stage one 64-key K/Ki/V tile (V from transposed layout), one commit group
    auto stage_tile = [&](int jt, float* sb) {
        const float* gkr = kr + base + (size_t)jt * 64 * DD;
        const float* gki = ki + base + (size_t)jt * 64 * DD;
        const float* gv  = vr + baseT + (size_t)jt * 64;   // row d, stride LL
#pragma unroll
        for (int i = 0; i < 4; i++) {
            int c = tid + (i << 8);            // 1024 chunks of 16B per matrix
            int r = c >> 4, c4 = (c & 15) << 2;
            cp16(s2u(sb + r * AP + c4),          gkr + r * DD + c4);
            cp16(s2u(sb + TK + r * AP + c4),     gki + r * DD + c4);
            cp16(s2u(sb + 2 * TK + r * AP + c4), gv + (size_t)r * LL + c4);
        }
        asm volatile("cp.async.commit_group;");
    };

    // ---- prologue: Q via cp.async into (buf1, P) regions, extract frags ----
    {
        const float* gqr = qr + base + (size_t)q0 * DD;
        const float* gqi = qi + base + (size_t)q0 * DD;
        float* sQr = sm + 3 * TK;
        float* sQi = sm + SPPOF;
#pragma unroll
        for (int i = 0; i < 8; i++) {
            int c = tid + (i << 8);
            int r = c >> 4, c4 = (c & 15) << 2;
            cp16(s2u(sQr + r * AP + c4), gqr + r * DD + c4);
            cp16(s2u(sQi + r * AP + c4), gqi + r * DD + c4);
        }
        asm volatile("cp.async.commit_group;");
        asm volatile("cp.async.wait_group 0;");
    }
    __syncthreads();

    uint32_t aQr[8][4], aQi[8][4];
#pragma unroll
    for (int kk = 0; kk < 8; kk++) {
        ldsm4(aQr[kk], s2u(sm + 3 * TK + (wq0 + ar) * AP + kk * 8 + ac));
        ldsm4(aQi[kk], s2u(sm + SPPOF  + (wq0 + ar) * AP + kk * 8 + ac));
    }
    __syncthreads();   // frags extracted before buf1/P reused

    float m_[2] = {-1e30f, -1e30f}, l_[2] = {0.f, 0.f};
    float oAcc[8][4];
#pragma unroll
    for (int ni = 0; ni < 8; ni++)
#pragma unroll
        for (int cc = 0; cc < 4; cc++) oAcc[ni][cc] = 0.f;

    const int jt0 = (qx >= 1) ? (2 * qx - 2) : 0;

    stage_tile(jt0, sm);
    asm volatile("cp.async.wait_group 0;");
    __syncthreads();

    for (int jt = jt0; jt < LL / 64; jt++) {
        const int ib = (jt - jt0) & 1;
        const float* cb = sm + ib * 3 * TK;

        if (jt + 1 < LL / 64)
            stage_tile(jt + 1, sm + (ib ^ 1) * 3 * TK);
        else
            asm volatile("cp.async.commit_group;");

        if (q0 + wq0 < jt * 64 + 192) {   // warp has unmasked keys this tile
            const float* sKr = cb;
            const float* sKi = cb + TK;
            const float* sV  = cb + 2 * TK;

            float s[8][4];
#pragma unroll
            for (int ni = 0; ni < 8; ni++)
#pragma unroll
                for (int cc = 0; cc < 4; cc++) s[ni][cc] = 0.f;

#pragma unroll
            for (int kk = 0; kk < 8; kk++) {
#pragma unroll
                for (int np = 0; np < 4; np++) {
                    uint32_t bkr[4], bki[4];
                    ldsm4(bkr, s2u(sKr + (np * 16 + br) * AP + kk * 8 + bc));
                    ldsm4(bki, s2u(sKi + (np * 16 + br) * AP + kk * 8 + bc));
                    mma8(s[2*np],   aQr[kk], bkr[0], bkr[1]);
                    mma8(s[2*np+1], aQr[kk], bkr[2], bkr[3]);
                    mma8(s[2*np],   aQi[kk], bki[0], bki[1]);
                    mma8(s[2*np+1], aQi[kk], bki[2], bki[3]);
                }
            }

#pragma unroll
            for (int ni = 0; ni < 8; ni++)
#pragma unroll
                for (int cc = 0; cc < 4; cc++) s[ni][cc] *= 0.125f;

            if (q0 + wq0 + 15 >= jt * 64 + 129) {   // band mask can bite
                int ig0 = q0 + wq0 + (lane >> 2);
                int jg  = jt * 64 + ((lane & 3) << 1);
#pragma unroll
                for (int ni = 0; ni < 8; ni++) {
                    int j0 = jg + (ni << 3);
                    if (ig0 - j0     >= 129) s[ni][0] = -1e30f;
                    if (ig0 - j0 - 1 >= 129) s[ni][1] = -1e30f;
                    if (ig0 + 8 - j0 >= 129) s[ni][2] = -1e30f;
                    if (ig0 + 7 - j0 >= 129) s[ni][3] = -1e30f;
                }
            }

            float mx0 = -1e30f, mx1 = -1e30f;
#pragma unroll
            for (int ni = 0; ni < 8; ni++) {
                mx0 = fmaxf(mx0, fmaxf(s[ni][0], s[ni][1]));
                mx1 = fmaxf(mx1, fmaxf(s[ni][2], s[ni][3]));
            }
            mx0 = fmaxf(mx0, __shfl_xor_sync(0xffffffffu, mx0, 1));
            mx0 = fmaxf(mx0, __shfl_xor_sync(0xffffffffu, mx0, 2));
            mx1 = fmaxf(mx1, __shfl_xor_sync(0xffffffffu, mx1, 1));
            mx1 = fmaxf(mx1, __shfl_xor_sync(0xffffffffu, mx1, 2));

            float nm0 = fmaxf(m_[0], mx0), nm1 = fmaxf(m_[1], mx1);
            float corr0 = __expf(m_[0] - nm0), corr1 = __expf(m_[1] - nm1);
            m_[0] = nm0; m_[1] = nm1;

            float rs0 = 0.f, rs1 = 0.f;
#pragma unroll
            for (int ni = 0; ni < 8; ni++) {
                s[ni][0] = __expf(s[ni][0] - nm0); rs0 += s[ni][0];
                s[ni][1] = __expf(s[ni][1] - nm0); rs0 += s[ni][1];
                s[ni][2] = __expf(s[ni][2] - nm1); rs1 += s[ni][2];
                s[ni][3] = __expf(s[ni][3] - nm1); rs1 += s[ni][3];
            }
            rs0 += __shfl_xor_sync(0xffffffffu, rs0, 1);
            rs0 += __shfl_xor_sync(0xffffffffu, rs0, 2);
            rs1 += __shfl_xor_sync(0xffffffffu, rs1, 1);
            rs1 += __shfl_xor_sync(0xffffffffu, rs1, 2);

            l_[0] = l_[0] * corr0 + rs0;
            l_[1] = l_[1] * corr1 + rs1;
#pragma unroll
            for (int ni = 0; ni < 8; ni++) {
                oAcc[ni][0] *= corr0; oAcc[ni][1] *= corr0;
                oAcc[ni][2] *= corr1; oAcc[ni][3] *= corr1;
            }

            {
                int r = wq0 + (lane >> 2);
                int c = (lane & 3) << 1;
                float* sP = sm + SPPOF;
#pragma unroll
                for (int ni = 0; ni < 8; ni++) {
                    *(float2*)&sP[r * AP + (ni << 3) + c] =
                        make_float2(f2tff(s[ni][0]), f2tff(s[ni][1]));
                    *(float2*)&sP[(r + 8) * AP + (ni << 3) + c] =
                        make_float2(f2tff(s[ni][2]), f2tff(s[ni][3]));
                }
            }
            __syncwarp();

#pragma unroll
            for (int kk = 0; kk < 8; kk++) {
                uint32_t pa[4];
                ldsm4(pa, s2u(sm + SPPOF + (wq0 + ar) * AP + kk * 8 + ac));
#pragma unroll
                for (int dp = 0; dp < 4; dp++) {
                    uint32_t bv[4];
                    ldsm4(bv, s2u(sV + (dp * 16 + br) * AP + kk * 8 + bc));
                    mma8(oAcc[2*dp],   pa, bv[0], bv[1]);
                    mma8(oAcc[2*dp+1], pa, bv[2], bv[3]);
                }
            }
        }

        asm volatile("cp.async.wait_group 0;");
        __syncthreads();
    }

    // ---- epilogue: normalize, round to tf32, write [B,L,E] ----
    float inv0 = 1.f / l_[0], inv1 = 1.f / l_[1];
    int b_ = bh >> 3, h = bh & 7;
    int r  = q0 + wq0 + (lane >> 2);
    int c  = (lane & 3) << 1;
#pragma unroll
    for (int ni = 0; ni < 8; ni++) {
        int d = (ni << 3) + c;
        *(float2*)(o + ((size_t)(b_ * LL + r)) * EE + h * DD + d) =
            make_float2(f2tff(oAcc[ni][0] * inv0), f2tff(oAcc[ni][1] * inv0));
        *(float2*)(o + ((size_t)(b_ * LL + r + 8)) * EE + h * DD + d) =
            make_float2(f2tff(oAcc[ni][2] * inv1), f2tff(oAcc[ni][3] * inv1));
    }
}

// ---------------------------------------------------------------------------
extern "C" void kernel_launch(void* const* d_in, const int* in_sizes, int n_in,
                              void* d_out, int out_size)
{
    (void)in_sizes; (void)n_in; (void)out_size;
    const float* query = (const float*)d_in[0];
    const float* key_  = (const float*)d_in[1];
    const float* value = (const float*)d_in[2];
    const float* qWr = (const float*)d_in[3];
    const float* qWi = (const float*)d_in[4];
    const float* qbr = (const float*)d_in[5];
    const float* qbi = (const float*)d_in[6];
    const float* kWr = (const float*)d_in[7];
    const float* kWi = (const float*)d_in[8];
    const float* kbr = (const float*)d_in[9];
    const float* kbi = (const float*)d_in[10];
    const float* vWr = (const float*)d_in[11];
    const float* vbr = (const float*)d_in[13];
    // d_in[12] (vWi), d_in[14] (vbi) unused: Im(V) discarded by reference.
    const float* oWr = (const float*)d_in[15];
    const float* oWi = (const float*)d_in[16];
    const float* obr = (const float*)d_in[17];
    const float* obi = (const float*)d_in[18];
    float* out = (float*)d_out;

    float *p_qr, *p_qi, *p_kr, *p_ki, *p_vr, *p_o;
    float *p_q, *p_k, *p_v;
    float *p_wqr, *p_wqi, *p_wkr, *p_wki, *p_wvr, *p_wor, *p_woi;
    cudaGetSymbolAddress((void**)&p_qr, g_qr);
    cudaGetSymbolAddress((void**)&p_qi, g_qi);
    cudaGetSymbolAddress((void**)&p_kr, g_kr);
    cudaGetSymbolAddress((void**)&p_ki, g_ki);
    cudaGetSymbolAddress((void**)&p_vr, g_vr);
    cudaGetSymbolAddress((void**)&p_o,  g_o);
    cudaGetSymbolAddress((void**)&p_q,  g_q);
    cudaGetSymbolAddress((void**)&p_k,  g_k);
    cudaGetSymbolAddress((void**)&p_v,  g_v);
    cudaGetSymbolAddress((void**)&p_wqr, g_wqr);
    cudaGetSymbolAddress((void**)&p_wqi, g_wqi);
    cudaGetSymbolAddress((void**)&p_wkr, g_wkr);
    cudaGetSymbolAddress((void**)&p_wki, g_wki);
    cudaGetSymbolAddress((void**)&p_wvr, g_wvr);
    cudaGetSymbolAddress((void**)&p_wor, g_wor);
    cudaGetSymbolAddress((void**)&p_woi, g_woi);

    cudaFuncSetAttribute(gemm_tc,
                         cudaFuncAttributeMaxDynamicSharedMemorySize, GEMM_SMEM);
    cudaFuncSetAttribute(attn_tc,
                         cudaFuncAttributeMaxDynamicSharedMemorySize, ATTN_SMEM);

    // ---- pre-round inputs + live weights to tf32 ----
    {
        const int NI4 = MROWS * EE / 4;
        const int NW4 = EE * EE / 4;
        RTab rt;
        rt.t[0] = {query, p_q,   NI4};
        rt.t[1] = {key_,  p_k,   NI4};
        rt.t[2] = {value, p_v,   NI4};
        rt.t[3] = {qWr,   p_wqr, NW4};
        rt.t[4] = {qWi,   p_wqi, NW4};
        rt.t[5] = {kWr,   p_wkr, NW4};
        rt.t[6] = {kWi,   p_wki, NW4};
        rt.t[7] = {vWr,   p_wvr, NW4};
        rt.t[8] = {oWr,   p_wor, NW4};
        rt.t[9] = {oWi,   p_woi, NW4};
        round_tf32_k<<<dim3(1024, 10), 256>>>(rt);
    }

    dim3 ggrid5(EE / 128, MROWS / 128, 5);   // (4, 64, 5)
    dim3 ggrid2(EE / 128, MROWS / 128, 2);

    {
        GJobs pj;
        pj.j[0] = {p_q, p_wqr, qbr, p_qr, 1};
        pj.j[1] = {p_q, p_wqi, qbi, p_qi, 1};
        pj.j[2] = {p_k, p_wkr, kbr, p_kr, 1};
        pj.j[3] = {p_k, p_wki, kbi, p_ki, 1};
        pj.j[4] = {p_v, p_wvr, vbr, p_vr, 2};   // V transposed
        gemm_tc<<<ggrid5, 256, GEMM_SMEM>>>(pj);
    }

    attn_tc<<<dim3(BHD, LL / 128), 256, ATTN_SMEM>>>(p_qr, p_qi, p_kr, p_ki,
                                                     p_vr, p_o);

    {
        GJobs oj;
        oj.j[0] = {p_o, p_wor, obr, out, 0};
        oj.j[1] = {p_o, p_woi, obi, out + (size_t)MROWS * EE, 0};
        oj.j[2] = oj.j[0]; oj.j[3] = oj.j[0]; oj.j[4] = oj.j[0];
        gemm_tc<<<ggrid2, 256, GEMM_SMEM>>>(oj);
    }
}

// round 9
// speedup vs baseline: 8.9068x; 1.9136x over previous
#include <cuda_runtime.h>
#include <cuda_fp16.h>
#include <cstdint>

#define LL 4096
#define EE 512
#define HH 8
#define DD 64
#define BBATCH 2
#define MROWS (BBATCH*LL)      // 8192
#define BHD (BBATCH*HH)        // 16

// Scratch (static device arrays: allocation-free rule) — fp16 everywhere
__device__ __half g_qr[BHD*LL*DD];
__device__ __half g_qi[BHD*LL*DD];
__device__ __half g_kr[BHD*LL*DD];
__device__ __half g_ki[BHD*LL*DD];
__device__ __half g_vr[BHD*DD*LL];   // TRANSPOSED: [B,H,D,L]
__device__ __half g_o [BBATCH*LL*EE];
// fp16 pre-converted inputs/weights
__device__ __half g_q[MROWS*EE];
__device__ __half g_k[MROWS*EE];
__device__ __half g_v[MROWS*EE];
__device__ __half g_wqr[EE*EE];
__device__ __half g_wqi[EE*EE];
__device__ __half g_wkr[EE*EE];
__device__ __half g_wki[EE*EE];
__device__ __half g_wvr[EE*EE];
__device__ __half g_wor[EE*EE];
__device__ __half g_woi[EE*EE];

// ---------------------------------------------------------------------------
// helpers
// ---------------------------------------------------------------------------
__device__ __forceinline__ void mma16(float* c, const uint32_t* a,
                                      uint32_t b0, uint32_t b1)
{
    asm volatile(
        "mma.sync.aligned.m16n8k16.row.col.f32.f16.f16.f32 "
        "{%0,%1,%2,%3}, {%4,%5,%6,%7}, {%8,%9}, {%0,%1,%2,%3};"
        : "+f"(c[0]), "+f"(c[1]), "+f"(c[2]), "+f"(c[3])
        : "r"(a[0]), "r"(a[1]), "r"(a[2]), "r"(a[3]), "r"(b0), "r"(b1));
}
__device__ __forceinline__ void cp16(uint32_t s, const void* g) {
    asm volatile("cp.async.cg.shared.global [%0], [%1], 16;" :: "r"(s), "l"(g));
}
__device__ __forceinline__ void ldsm4(uint32_t* r, uint32_t a) {
    asm volatile("ldmatrix.sync.aligned.m8n8.x4.shared.b16 {%0,%1,%2,%3}, [%4];"
        : "=r"(r[0]), "=r"(r[1]), "=r"(r[2]), "=r"(r[3]) : "r"(a));
}
__device__ __forceinline__ uint32_t s2u(const void* p) {
    return (uint32_t)__cvta_generic_to_shared(p);
}

// ---------------------------------------------------------------------------
// Pre-convert fp32 -> fp16 (elementwise, float4 in, half2 x2 out).
// ---------------------------------------------------------------------------
struct RPair { const float* s; __half* d; int n4; };
struct RTab  { RPair t[10]; };

__global__ void __launch_bounds__(256)
conv_f16_k(RTab tab)
{
    RPair p = tab.t[blockIdx.y];
    int stride = gridDim.x * blockDim.x;
    for (int i = blockIdx.x * blockDim.x + threadIdx.x; i < p.n4; i += stride) {
        float4 v = ((const float4*)p.s)[i];
        __half2* d2 = (__half2*)p.d;
        d2[2*i]   = __floats2half2_rn(v.x, v.y);
        d2[2*i+1] = __floats2half2_rn(v.z, v.w);
    }
}

// ---------------------------------------------------------------------------
// fp16 GEMM: C[M,N] = A[M,K] @ W[N,K]^T + bias, M=8192, N=K=512.
// BM=BN=128, BK=32, 256 threads, 3-stage cp.async ring, m16n8k16 mma.
// mode: 0 = flat [M,E] fp32 out; 1 = head [B,H,L,D] fp16; 2 = headT [B,H,D,L] fp16.
// ---------------------------------------------------------------------------
struct GJob  { const __half* A; const __half* W; const float* bias; void* C; int mode; };
struct GJobs { GJob j[5]; };

#define GKS 40                         // halves per smem row (32 + 8 pad)
#define GSTAGE (2*128*GKS)             // halves per stage (A then B)
#define GEMM_SMEM (3*GSTAGE*2)         // 61440 B

__global__ void __launch_bounds__(256, 2)
gemm_h(GJobs jobs)
{
    extern __shared__ __half smh[];
    const GJob jb = jobs.j[blockIdx.z];
    const __half* __restrict__ A = jb.A;
    const __half* __restrict__ W = jb.W;

    const int tid  = threadIdx.x;
    const int lane = tid & 31, warp = tid >> 5;
    const int row0 = blockIdx.y << 7;
    const int col0 = blockIdx.x << 7;
    const int wm = (warp >> 2) << 6;     // 0/64
    const int wn = (warp & 3) << 5;      // 0/32/64/96

    const int g  = lane >> 3, rr = lane & 7;
    const int ar = (g & 1) * 8 + rr, ac = (g >> 1) * 8;   // halves
    const int br = (g >> 1) * 8 + rr, bc = (g & 1) * 8;   // halves

    float acc[4][4][4];
#pragma unroll
    for (int mi = 0; mi < 4; mi++)
#pragma unroll
        for (int ni = 0; ni < 4; ni++)
#pragma unroll
            for (int cc = 0; cc < 4; cc++) acc[mi][ni][cc] = 0.f;

    auto load_tile = [&](int t, int buf) {
        const int k0 = t << 5;                 // halves
        __half* a = smh + buf * GSTAGE;
        __half* b = a + 128 * GKS;
#pragma unroll
        for (int i = 0; i < 4; i++) {
            int idx = tid + (i << 8);          // 0..1023
            int mat = idx >> 9;                // 0:A rows, 1:B rows
            int c   = idx & 511;
            int row = c >> 2, ch = c & 3;      // 4 chunks of 8 halves per row
            const __half* gp = (mat ? W + (size_t)(col0 + row) * EE
                                    : A + (size_t)(row0 + row) * EE)
                               + k0 + (ch << 3);
            cp16(s2u((mat ? b : a) + row * GKS + (ch << 3)), gp);
        }
        asm volatile("cp.async.commit_group;");
    };

    load_tile(0, 0);
    load_tile(1, 1);

    int buf = 0;
    for (int t = 0; t < 16; t++) {
        asm volatile("cp.async.wait_group 1;");
        __syncthreads();
        if (t + 2 < 16) load_tile(t + 2, (t + 2) % 3);
        else            asm volatile("cp.async.commit_group;");

        const __half* a = smh + buf * GSTAGE;
        const __half* b = a + 128 * GKS;
#pragma unroll
        for (int kk = 0; kk < 2; kk++) {       // two k16 steps
            uint32_t af[4][4], bf[2][4];
#pragma unroll
            for (int mi = 0; mi < 4; mi++)
                ldsm4(af[mi], s2u(a + (wm + mi * 16 + ar) * GKS + kk * 16 + ac));
#pragma unroll
            for (int np = 0; np < 2; np++)
                ldsm4(bf[np], s2u(b + (wn + np * 16 + br) * GKS + kk * 16 + bc));
#pragma unroll
            for (int mi = 0; mi < 4; mi++)
#pragma unroll
                for (int np = 0; np < 2; np++) {
                    mma16(acc[mi][2*np],   af[mi], bf[np][0], bf[np][1]);
                    mma16(acc[mi][2*np+1], af[mi], bf[np][2], bf[np][3]);
                }
        }
        buf = (buf + 1) % 3;
        __syncthreads();
    }

    // epilogue
#pragma unroll
    for (int mi = 0; mi < 4; mi++) {
#pragma unroll
        for (int ni = 0; ni < 4; ni++) {
            int r  = row0 + wm + mi * 16 + (lane >> 2);
            int cL = col0 + wn + ni * 8 + ((lane & 3) << 1);
            float b0 = jb.bias[cL], b1 = jb.bias[cL + 1];
            float a0 = acc[mi][ni][0] + b0, a1 = acc[mi][ni][1] + b1;
            float a2 = acc[mi][ni][2] + b0, a3 = acc[mi][ni][3] + b1;
            int b_ = r >> 12, l = r & (LL - 1);
            int h  = cL >> 6, d = cL & 63;
            if (jb.mode == 0) {
                float* C = (float*)jb.C;
                *(float2*)(C + (size_t)r * EE + cL)       = make_float2(a0, a1);
                *(float2*)(C + (size_t)(r + 8) * EE + cL) = make_float2(a2, a3);
            } else if (jb.mode == 1) {
                __half* C = (__half*)jb.C;
                size_t o = ((size_t)((b_ * HH + h) * LL + l)) * DD + d;
                *(__half2*)(C + o)          = __floats2half2_rn(a0, a1);
                *(__half2*)(C + o + 8 * DD) = __floats2half2_rn(a2, a3);
            } else {
                __half* C = (__half*)jb.C;   // headT [B,H,D,L]
                size_t o = ((size_t)((b_ * HH + h) * DD + d)) * LL + l;
                C[o]          = __float2half_rn(a0);
                C[o + LL]     = __float2half_rn(a1);
                C[o + 8]      = __float2half_rn(a2);
                C[o + LL + 8] = __float2half_rn(a3);
            }
        }
    }
}

// ---------------------------------------------------------------------------
// Flash attention, fp16 m16n8k16 mma + ldmatrix, cp.async double-buffered.
// 128 queries per block, 8 warps; warp w owns rows [w*16, w*16+16).
// grid = (bh, qx): heavy (low-qx) blocks first. 2 CTAs/SM.
// ---------------------------------------------------------------------------
#define AP 72                              // halves per smem row (64 + 8 pad)
#define TK (64*AP)                         // halves per 64-row tile
#define SPPOF (6*TK)                       // P region: 128*AP halves
#define ATTN_SMEM ((6*64 + 128) * AP * 2)  // 73728 B

__global__ void __launch_bounds__(256, 2)
attn_h(const __half* __restrict__ qr, const __half* __restrict__ qi,
       const __half* __restrict__ kr, const __half* __restrict__ ki,
       const __half* __restrict__ vr, __half* __restrict__ o)
{
    extern __shared__ __half sh[];
    const int tid = threadIdx.x, lane = tid & 31, warp = tid >> 5;
    const int bh = blockIdx.x;
    const int qx = blockIdx.y;
    const int q0 = qx << 7;
    const size_t base  = (size_t)bh * LL * DD;
    const size_t baseT = (size_t)bh * DD * LL;
    const int wq0 = warp << 4;

    const int g  = lane >> 3, rr = lane & 7;
    const int ar = (g & 1) * 8 + rr, ac = (g >> 1) * 8;
    const int br = (g >> 1) * 8 + rr, bc = (g & 1) * 8;

    // stage one 64-key K/Ki/V tile (V from transposed layout)
    auto stage_tile = [&](int jt, __half* sb) {
        const __half* gkr = kr + base + (size_t)jt * 64 * DD;
        const __half* gki = ki + base + (size_t)jt * 64 * DD;
        const __half* gv  = vr + baseT + (size_t)jt * 64;
#pragma unroll
        for (int i = 0; i < 6; i++) {
            int idx = tid + (i << 8);          // 0..1535
            int mat = idx / 512;
            int c   = idx & 511;
            int r = c >> 3, ch = c & 7;        // 8 chunks of 8 halves per row
            const __half* gp = (mat == 0) ? gkr + r * DD + (ch << 3)
                             : (mat == 1) ? gki + r * DD + (ch << 3)
                                          : gv + (size_t)r * LL + (ch << 3);
            cp16(s2u(sb + mat * TK + r * AP + (ch << 3)), gp);
        }
        asm volatile("cp.async.commit_group;");
    };

    // ---- prologue: Q via cp.async (Qr->P region, Qi->buf1), extract frags ---
    {
        const __half* gqr = qr + base + (size_t)q0 * DD;
        const __half* gqi = qi + base + (size_t)q0 * DD;
        __half* sQr = sh + SPPOF;
        __half* sQi = sh + 3 * TK;
#pragma unroll
        for (int i = 0; i < 8; i++) {
            int idx = tid + (i << 8);          // 0..2047
            int mat = idx >> 10;
            int c   = idx & 1023;
            int r = c >> 3, ch = c & 7;
            const __half* gp = (mat ? gqi + r * DD + (ch << 3)
                                    : gqr + r * DD + (ch << 3));
            cp16(s2u((mat ? sQi : sQr) + r * AP + (ch << 3)), gp);
        }
        asm volatile("cp.async.commit_group;");
        asm volatile("cp.async.wait_group 0;");
    }
    __syncthreads();

    uint32_t aQr[4][4], aQi[4][4];
#pragma unroll
    for (int kk = 0; kk < 4; kk++) {
        ldsm4(aQr[kk], s2u(sh + SPPOF  + (wq0 + ar) * AP + kk * 16 + ac));
        ldsm4(aQi[kk], s2u(sh + 3 * TK + (wq0 + ar) * AP + kk * 16 + ac));
    }
    __syncthreads();   // frags extracted before buf1/P reused

    float m_[2] = {-1e30f, -1e30f}, l_[2] = {0.f, 0.f};
    float oAcc[8][4];
#pragma unroll
    for (int ni = 0; ni < 8; ni++)
#pragma unroll
        for (int cc = 0; cc < 4; cc++) oAcc[ni][cc] = 0.f;

    const int jt0 = (qx >= 1) ? (2 * qx - 2) : 0;

    stage_tile(jt0, sh);
    asm volatile("cp.async.wait_group 0;");
    __syncthreads();

    for (int jt = jt0; jt < LL / 64; jt++) {
        const int ib = (jt - jt0) & 1;
        const __half* cb = sh + ib * 3 * TK;

        if (jt + 1 < LL / 64)
            stage_tile(jt + 1, sh + (ib ^ 1) * 3 * TK);
        else
            asm volatile("cp.async.commit_group;");

        if (q0 + wq0 < jt * 64 + 192) {   // warp has unmasked keys this tile
            const __half* sKr = cb;
            const __half* sKi = cb + TK;
            const __half* sV  = cb + 2 * TK;

            float s[8][4];
#pragma unroll
            for (int ni = 0; ni < 8; ni++)
#pragma unroll
                for (int cc = 0; cc < 4; cc++) s[ni][cc] = 0.f;

#pragma unroll
            for (int kk = 0; kk < 4; kk++) {
#pragma unroll
                for (int np = 0; np < 4; np++) {
                    uint32_t bkr[4], bki[4];
                    ldsm4(bkr, s2u(sKr + (np * 16 + br) * AP + kk * 16 + bc));
                    ldsm4(bki, s2u(sKi + (np * 16 + br) * AP + kk * 16 + bc));
                    mma16(s[2*np],   aQr[kk], bkr[0], bkr[1]);
                    mma16(s[2*np+1], aQr[kk], bkr[2], bkr[3]);
                    mma16(s[2*np],   aQi[kk], bki[0], bki[1]);
                    mma16(s[2*np+1], aQi[kk], bki[2], bki[3]);
                }
            }

#pragma unroll
            for (int ni = 0; ni < 8; ni++)
#pragma unroll
                for (int cc = 0; cc < 4; cc++) s[ni][cc] *= 0.125f;

            if (q0 + wq0 + 15 >= jt * 64 + 129) {   // band mask can bite
                int ig0 = q0 + wq0 + (lane >> 2);
                int jg  = jt * 64 + ((lane & 3) << 1);
#pragma unroll
                for (int ni = 0; ni < 8; ni++) {
                    int j0 = jg + (ni << 3);
                    if (ig0 - j0     >= 129) s[ni][0] = -1e30f;
                    if (ig0 - j0 - 1 >= 129) s[ni][1] = -1e30f;
                    if (ig0 + 8 - j0 >= 129) s[ni][2] = -1e30f;
                    if (ig0 + 7 - j0 >= 129) s[ni][3] = -1e30f;
                }
            }

            float mx0 = -1e30f, mx1 = -1e30f;
#pragma unroll
            for (int ni = 0; ni < 8; ni++) {
                mx0 = fmaxf(mx0, fmaxf(s[ni][0], s[ni][1]));
                mx1 = fmaxf(mx1, fmaxf(s[ni][2], s[ni][3]));
            }
            mx0 = fmaxf(mx0, __shfl_xor_sync(0xffffffffu, mx0, 1));
            mx0 = fmaxf(mx0, __shfl_xor_sync(0xffffffffu, mx0, 2));
            mx1 = fmaxf(mx1, __shfl_xor_sync(0xffffffffu, mx1, 1));
            mx1 = fmaxf(mx1, __shfl_xor_sync(0xffffffffu, mx1, 2));

            float nm0 = fmaxf(m_[0], mx0), nm1 = fmaxf(m_[1], mx1);
            float corr0 = __expf(m_[0] - nm0), corr1 = __expf(m_[1] - nm1);
            m_[0] = nm0; m_[1] = nm1;

            float rs0 = 0.f, rs1 = 0.f;
#pragma unroll
            for (int ni = 0; ni < 8; ni++) {
                s[ni][0] = __expf(s[ni][0] - nm0); rs0 += s[ni][0];
                s[ni][1] = __expf(s[ni][1] - nm0); rs0 += s[ni][1];
                s[ni][2] = __expf(s[ni][2] - nm1); rs1 += s[ni][2];
                s[ni][3] = __expf(s[ni][3] - nm1); rs1 += s[ni][3];
            }
            rs0 += __shfl_xor_sync(0xffffffffu, rs0, 1);
            rs0 += __shfl_xor_sync(0xffffffffu, rs0, 2);
            rs1 += __shfl_xor_sync(0xffffffffu, rs1, 1);
            rs1 += __shfl_xor_sync(0xffffffffu, rs1, 2);

            l_[0] = l_[0] * corr0 + rs0;
            l_[1] = l_[1] * corr1 + rs1;
#pragma unroll
            for (int ni = 0; ni < 8; ni++) {
                oAcc[ni][0] *= corr0; oAcc[ni][1] *= corr0;
                oAcc[ni][2] *= corr1; oAcc[ni][3] *= corr1;
            }

            // ---- P -> smem fp16 (warp-private rows), PV ----
            {
                int r = wq0 + (lane >> 2);
                int c = (lane & 3) << 1;
                __half* sP = sh + SPPOF;
#pragma unroll
                for (int ni = 0; ni < 8; ni++) {
                    *(__half2*)&sP[r * AP + (ni << 3) + c] =
                        __floats2half2_rn(s[ni][0], s[ni][1]);
                    *(__half2*)&sP[(r + 8) * AP + (ni << 3) + c] =
                        __floats2half2_rn(s[ni][2], s[ni][3]);
                }
            }
            __syncwarp();

#pragma unroll
            for (int kk = 0; kk < 4; kk++) {
                uint32_t pa[4];
                ldsm4(pa, s2u(sh + SPPOF + (wq0 + ar) * AP + kk * 16 + ac));
#pragma unroll
                for (int dp = 0; dp < 4; dp++) {
                    uint32_t bv[4];
                    ldsm4(bv, s2u(sV + (dp * 16 + br) * AP + kk * 16 + bc));
                    mma16(oAcc[2*dp],   pa, bv[0], bv[1]);
                    mma16(oAcc[2*dp+1], pa, bv[2], bv[3]);
                }
            }
        }

        asm volatile("cp.async.wait_group 0;");
        __syncthreads();
    }

    // ---- epilogue: normalize, write fp16 [B,L,E] ----
    float inv0 = 1.f / l_[0], inv1 = 1.f / l_[1];
    int b_ = bh >> 3, h = bh & 7;
    int r  = q0 + wq0 + (lane >> 2);
    int c  = (lane & 3) << 1;
#pragma unroll
    for (int ni = 0; ni < 8; ni++) {
        int d = (ni << 3) + c;
        *(__half2*)(o + ((size_t)(b_ * LL + r)) * EE + h * DD + d) =
            __floats2half2_rn(oAcc[ni][0] * inv0, oAcc[ni][1] * inv0);
        *(__half2*)(o + ((size_t)(b_ * LL + r + 8)) * EE + h * DD + d) =
            __floats2half2_rn(oAcc[ni][2] * inv1, oAcc[ni][3] * inv1);
    }
}

// ---------------------------------------------------------------------------
extern "C" void kernel_launch(void* const* d_in, const int* in_sizes, int n_in,
                              void* d_out, int out_size)
{
    (void)in_sizes; (void)n_in; (void)out_size;
    const float* query = (const float*)d_in[0];
    const float* key_  = (const float*)d_in[1];
    const float* value = (const float*)d_in[2];
    const float* qWr = (const float*)d_in[3];
    const float* qWi = (const float*)d_in[4];
    const float* qbr = (const float*)d_in[5];
    const float* qbi = (const float*)d_in[6];
    const float* kWr = (const float*)d_in[7];
    const float* kWi = (const float*)d_in[8];
    const float* kbr = (const float*)d_in[9];
    const float* kbi = (const float*)d_in[10];
    const float* vWr = (const float*)d_in[11];
    const float* vbr = (const float*)d_in[13];
    // d_in[12] (vWi), d_in[14] (vbi) unused: Im(V) discarded by reference.
    const float* oWr = (const float*)d_in[15];
    const float* oWi = (const float*)d_in[16];
    const float* obr = (const float*)d_in[17];
    const float* obi = (const float*)d_in[18];
    float* out = (float*)d_out;

    __half *p_qr, *p_qi, *p_kr, *p_ki, *p_vr, *p_o;
    __half *p_q, *p_k, *p_v;
    __half *p_wqr, *p_wqi, *p_wkr, *p_wki, *p_wvr, *p_wor, *p_woi;
    cudaGetSymbolAddress((void**)&p_qr, g_qr);
    cudaGetSymbolAddress((void**)&p_qi, g_qi);
    cudaGetSymbolAddress((void**)&p_kr, g_kr);
    cudaGetSymbolAddress((void**)&p_ki, g_ki);
    cudaGetSymbolAddress((void**)&p_vr, g_vr);
    cudaGetSymbolAddress((void**)&p_o,  g_o);
    cudaGetSymbolAddress((void**)&p_q,  g_q);
    cudaGetSymbolAddress((void**)&p_k,  g_k);
    cudaGetSymbolAddress((void**)&p_v,  g_v);
    cudaGetSymbolAddress((void**)&p_wqr, g_wqr);
    cudaGetSymbolAddress((void**)&p_wqi, g_wqi);
    cudaGetSymbolAddress((void**)&p_wkr, g_wkr);
    cudaGetSymbolAddress((void**)&p_wki, g_wki);
    cudaGetSymbolAddress((void**)&p_wvr, g_wvr);
    cudaGetSymbolAddress((void**)&p_wor, g_wor);
    cudaGetSymbolAddress((void**)&p_woi, g_woi);

    cudaFuncSetAttribute(gemm_h,
                         cudaFuncAttributeMaxDynamicSharedMemorySize, GEMM_SMEM);
    cudaFuncSetAttribute(attn_h,
                         cudaFuncAttributeMaxDynamicSharedMemorySize, ATTN_SMEM);

    // ---- pre-convert inputs + live weights to fp16 ----
    {
        const int NI4 = MROWS * EE / 4;
        const int NW4 = EE * EE / 4;
        RTab rt;
        rt.t[0] = {query, p_q,   NI4};
        rt.t[1] = {key_,  p_k,   NI4};
        rt.t[2] = {value, p_v,   NI4};
        rt.t[3] = {qWr,   p_wqr, NW4};
        rt.t[4] = {qWi,   p_wqi, NW4};
        rt.t[5] = {kWr,   p_wkr, NW4};
        rt.t[6] = {kWi,   p_wki, NW4};
        rt.t[7] = {vWr,   p_wvr, NW4};
        rt.t[8] = {oWr,   p_wor, NW4};
        rt.t[9] = {oWi,   p_woi, NW4};
        conv_f16_k<<<dim3(1024, 10), 256>>>(rt);
    }

    dim3 ggrid5(EE / 128, MROWS / 128, 5);   // (4, 64, 5)
    dim3 ggrid2(EE / 128, MROWS / 128, 2);

    {
        GJobs pj;
        pj.j[0] = {p_q, p_wqr, qbr, p_qr, 1};
        pj.j[1] = {p_q, p_wqi, qbi, p_qi, 1};
        pj.j[2] = {p_k, p_wkr, kbr, p_kr, 1};
        pj.j[3] = {p_k, p_wki, kbi, p_ki, 1};
        pj.j[4] = {p_v, p_wvr, vbr, p_vr, 2};   // V transposed
        gemm_h<<<ggrid5, 256, GEMM_SMEM>>>(pj);
    }

    attn_h<<<dim3(BHD, LL / 128), 256, ATTN_SMEM>>>(p_qr, p_qi, p_kr, p_ki,
                                                    p_vr, p_o);

    {
        GJobs oj;
        oj.j[0] = {p_o, p_wor, obr, out, 0};
        oj.j[1] = {p_o, p_woi, obi, out + (size_t)MROWS * EE, 0};
        oj.j[2] = oj.j[0]; oj.j[3] = oj.j[0]; oj.j[4] = oj.j[0];
        gemm_h<<<ggrid2, 256, GEMM_SMEM>>>(oj);
    }
}

// round 10
// speedup vs baseline: 8.9427x; 1.0040x over previous
#include <cuda_runtime.h>
#include <cuda_fp16.h>
#include <cstdint>

#define LL 4096
#define EE 512
#define HH 8
#define DD 64
#define BBATCH 2
#define MROWS (BBATCH*LL)      // 8192
#define BHD (BBATCH*HH)        // 16

// Scratch (static device arrays: allocation-free rule) — fp16 everywhere
__device__ __half g_qr[BHD*LL*DD];
__device__ __half g_qi[BHD*LL*DD];
__device__ __half g_kr[BHD*LL*DD];
__device__ __half g_ki[BHD*LL*DD];
__device__ __half g_vr[BHD*DD*LL];   // TRANSPOSED: [B,H,D,L]
__device__ __half g_o [BBATCH*LL*EE];
// fp16 pre-converted inputs/weights
__device__ __half g_q[MROWS*EE];
__device__ __half g_k[MROWS*EE];
__device__ __half g_v[MROWS*EE];
__device__ __half g_wqr[EE*EE];
__device__ __half g_wqi[EE*EE];
__device__ __half g_wkr[EE*EE];
__device__ __half g_wki[EE*EE];
__device__ __half g_wvr[EE*EE];
__device__ __half g_wor[EE*EE];
__device__ __half g_woi[EE*EE];

// ---------------------------------------------------------------------------
// helpers
// ---------------------------------------------------------------------------
__device__ __forceinline__ void mma16(float* c, const uint32_t* a,
                                      uint32_t b0, uint32_t b1)
{
    asm volatile(
        "mma.sync.aligned.m16n8k16.row.col.f32.f16.f16.f32 "
        "{%0,%1,%2,%3}, {%4,%5,%6,%7}, {%8,%9}, {%0,%1,%2,%3};"
        : "+f"(c[0]), "+f"(c[1]), "+f"(c[2]), "+f"(c[3])
        : "r"(a[0]), "r"(a[1]), "r"(a[2]), "r"(a[3]), "r"(b0), "r"(b1));
}
__device__ __forceinline__ void cp16(uint32_t s, const void* g) {
    asm volatile("cp.async.cg.shared.global [%0], [%1], 16;" :: "r"(s), "l"(g));
}
__device__ __forceinline__ void ldsm4(uint32_t* r, uint32_t a) {
    asm volatile("ldmatrix.sync.aligned.m8n8.x4.shared.b16 {%0,%1,%2,%3}, [%4];"
        : "=r"(r[0]), "=r"(r[1]), "=r"(r[2]), "=r"(r[3]) : "r"(a));
}
__device__ __forceinline__ uint32_t s2u(const void* p) {
    return (uint32_t)__cvta_generic_to_shared(p);
}

// ---------------------------------------------------------------------------
// Pre-convert fp32 -> fp16 (elementwise, float4 in, half2 x2 out).
// ---------------------------------------------------------------------------
struct RPair { const float* s; __half* d; int n4; };
struct RTab  { RPair t[10]; };

__global__ void __launch_bounds__(256)
conv_f16_k(RTab tab)
{
    RPair p = tab.t[blockIdx.y];
    int stride = gridDim.x * blockDim.x;
    for (int i = blockIdx.x * blockDim.x + threadIdx.x; i < p.n4; i += stride) {
        float4 v = ((const float4*)p.s)[i];
        __half2* d2 = (__half2*)p.d;
        d2[2*i]   = __floats2half2_rn(v.x, v.y);
        d2[2*i+1] = __floats2half2_rn(v.z, v.w);
    }
}

// ---------------------------------------------------------------------------
// fp16 GEMM: C[M,N] = A[M,K] @ W[N,K]^T + bias, M=8192, N=K=512.
// BM=BN=128, BK=32, 256 threads, 3-stage cp.async ring, m16n8k16 mma.
// mode: 0 = flat [M,E] fp32 out; 1 = head [B,H,L,D] fp16; 2 = headT [B,H,D,L] fp16.
// ---------------------------------------------------------------------------
struct GJob  { const __half* A; const __half* W; const float* bias; void* C; int mode; };
struct GJobs { GJob j[5]; };

#define GKS 40                         // halves per smem row (32 + 8 pad)
#define GSTAGE (2*128*GKS)             // halves per stage (A then B)
#define GEMM_SMEM (3*GSTAGE*2)         // 61440 B

__global__ void __launch_bounds__(256, 2)
gemm_h(GJobs jobs)
{
    extern __shared__ __half smh[];
    const GJob jb = jobs.j[blockIdx.z];
    const __half* __restrict__ A = jb.A;
    const __half* __restrict__ W = jb.W;

    const int tid  = threadIdx.x;
    const int lane = tid & 31, warp = tid >> 5;
    const int row0 = blockIdx.y << 7;
    const int col0 = blockIdx.x << 7;
    const int wm = (warp >> 2) << 6;     // 0/64
    const int wn = (warp & 3) << 5;      // 0/32/64/96

    const int g  = lane >> 3, rr = lane & 7;
    const int ar = (g & 1) * 8 + rr, ac = (g >> 1) * 8;   // halves
    const int br = (g >> 1) * 8 + rr, bc = (g & 1) * 8;   // halves

    float acc[4][4][4];
#pragma unroll
    for (int mi = 0; mi < 4; mi++)
#pragma unroll
        for (int ni = 0; ni < 4; ni++)
#pragma unroll
            for (int cc = 0; cc < 4; cc++) acc[mi][ni][cc] = 0.f;

    auto load_tile = [&](int t, int buf) {
        const int k0 = t << 5;                 // halves
        __half* a = smh + buf * GSTAGE;
        __half* b = a + 128 * GKS;
#pragma unroll
        for (int i = 0; i < 4; i++) {
            int idx = tid + (i << 8);          // 0..1023
            int mat = idx >> 9;                // 0:A rows, 1:B rows
            int c   = idx & 511;
            int row = c >> 2, ch = c & 3;      // 4 chunks of 8 halves per row
            const __half* gp = (mat ? W + (size_t)(col0 + row) * EE
                                    : A + (size_t)(row0 + row) * EE)
                               + k0 + (ch << 3);
            cp16(s2u((mat ? b : a) + row * GKS + (ch << 3)), gp);
        }
        asm volatile("cp.async.commit_group;");
    };

    load_tile(0, 0);
    load_tile(1, 1);

    int buf = 0;
    for (int t = 0; t < 16; t++) {
        asm volatile("cp.async.wait_group 1;");
        __syncthreads();
        if (t + 2 < 16) load_tile(t + 2, (t + 2) % 3);
        else            asm volatile("cp.async.commit_group;");

        const __half* a = smh + buf * GSTAGE;
        const __half* b = a + 128 * GKS;
#pragma unroll
        for (int kk = 0; kk < 2; kk++) {       // two k16 steps
            uint32_t af[4][4], bf[2][4];
#pragma unroll
            for (int mi = 0; mi < 4; mi++)
                ldsm4(af[mi], s2u(a + (wm + mi * 16 + ar) * GKS + kk * 16 + ac));
#pragma unroll
            for (int np = 0; np < 2; np++)
                ldsm4(bf[np], s2u(b + (wn + np * 16 + br) * GKS + kk * 16 + bc));
#pragma unroll
            for (int mi = 0; mi < 4; mi++)
#pragma unroll
                for (int np = 0; np < 2; np++) {
                    mma16(acc[mi][2*np],   af[mi], bf[np][0], bf[np][1]);
                    mma16(acc[mi][2*np+1], af[mi], bf[np][2], bf[np][3]);
                }
        }
        buf = (buf + 1) % 3;
        __syncthreads();
    }

    // epilogue
#pragma unroll
    for (int mi = 0; mi < 4; mi++) {
#pragma unroll
        for (int ni = 0; ni < 4; ni++) {
            int r  = row0 + wm + mi * 16 + (lane >> 2);
            int cL = col0 + wn + ni * 8 + ((lane & 3) << 1);
            float b0 = jb.bias[cL], b1 = jb.bias[cL + 1];
            float a0 = acc[mi][ni][0] + b0, a1 = acc[mi][ni][1] + b1;
            float a2 = acc[mi][ni][2] + b0, a3 = acc[mi][ni][3] + b1;
            int b_ = r >> 12, l = r & (LL - 1);
            int h  = cL >> 6, d = cL & 63;
            if (jb.mode == 0) {
                float* C = (float*)jb.C;
                *(float2*)(C + (size_t)r * EE + cL)       = make_float2(a0, a1);
                *(float2*)(C + (size_t)(r + 8) * EE + cL) = make_float2(a2, a3);
            } else if (jb.mode == 1) {
                __half* C = (__half*)jb.C;
                size_t o = ((size_t)((b_ * HH + h) * LL + l)) * DD + d;
                *(__half2*)(C + o)          = __floats2half2_rn(a0, a1);
                *(__half2*)(C + o + 8 * DD) = __floats2half2_rn(a2, a3);
            } else {
                __half* C = (__half*)jb.C;   // headT [B,H,D,L]
                size_t o = ((size_t)((b_ * HH + h) * DD + d)) * LL + l;
                C[o]          = __float2half_rn(a0);
                C[o + LL]     = __float2half_rn(a1);
                C[o + 8]      = __float2half_rn(a2);
                C[o + LL + 8] = __float2half_rn(a3);
            }
        }
    }
}

// ---------------------------------------------------------------------------
// Flash attention, fp16 m16n8k16 mma + ldmatrix, cp.async double-buffered.
// 128 queries per block, 8 warps; warp w owns rows [w*16, w*16+16).
// grid = (bh, qx): heavy (low-qx) blocks first. 2 CTAs/SM.
// ---------------------------------------------------------------------------
#define AP 72                              // halves per smem row (64 + 8 pad)
#define TK (64*AP)                         // halves per 64-row tile
#define SPPOF (6*TK)                       // P region: 128*AP halves
#define ATTN_SMEM ((6*64 + 128) * AP * 2)  // 73728 B

__global__ void __launch_bounds__(256, 2)
attn_h(const __half* __restrict__ qr, const __half* __restrict__ qi,
       const __half* __restrict__ kr, const __half* __restrict__ ki,
       const __half* __restrict__ vr, __half* __restrict__ o)
{
    extern __shared__ __half sh[];
    const int tid = threadIdx.x, lane = tid & 31, warp = tid >> 5;
    const int bh = blockIdx.x;
    const int qx = blockIdx.y;
    const int q0 = qx << 7;
    const size_t base  = (size_t)bh * LL * DD;
    const size_t baseT = (size_t)bh * DD * LL;
    const int wq0 = warp << 4;

    const int g  = lane >> 3, rr = lane & 7;
    const int ar = (g & 1) * 8 + rr, ac = (g >> 1) * 8;
    const int br = (g >> 1) * 8 + rr, bc = (g & 1) * 8;

    // stage one 64-key K/Ki/V tile (V from transposed layout)
    auto stage_tile = [&](int jt, __half* sb) {
        const __half* gkr = kr + base + (size_t)jt * 64 * DD;
        const __half* gki = ki + base + (size_t)jt * 64 * DD;
        const __half* gv  = vr + baseT + (size_t)jt * 64;
#pragma unroll
        for (int i = 0; i < 6; i++) {
            int idx = tid + (i << 8);          // 0..1535
            int mat = idx / 512;
            int c   = idx & 511;
            int r = c >> 3, ch = c & 7;        // 8 chunks of 8 halves per row
            const __half* gp = (mat == 0) ? gkr + r * DD + (ch << 3)
                             : (mat == 1) ? gki + r * DD + (ch << 3)
                                          : gv + (size_t)r * LL + (ch << 3);
            cp16(s2u(sb + mat * TK + r * AP + (ch << 3)), gp);
        }
        asm volatile("cp.async.commit_group;");
    };

    // ---- prologue: Q via cp.async (Qr->P region, Qi->buf1), extract frags ---
    {
        const __half* gqr = qr + base + (size_t)q0 * DD;
        const __half* gqi = qi + base + (size_t)q0 * DD;
        __half* sQr = sh + SPPOF;
        __half* sQi = sh + 3 * TK;
#pragma unroll
        for (int i = 0; i < 8; i++) {
            int idx = tid + (i << 8);          // 0..2047
            int mat = idx >> 10;
            int c   = idx & 1023;
            int r = c >> 3, ch = c & 7;
            const __half* gp = (mat ? gqi + r * DD + (ch << 3)
                                    : gqr + r * DD + (ch << 3));
            cp16(s2u((mat ? sQi : sQr) + r * AP + (ch << 3)), gp);
        }
        asm volatile("cp.async.commit_group;");
        asm volatile("cp.async.wait_group 0;");
    }
    __syncthreads();

    uint32_t aQr[4][4], aQi[4][4];
#pragma unroll
    for (int kk = 0; kk < 4; kk++) {
        ldsm4(aQr[kk], s2u(sh + SPPOF  + (wq0 + ar) * AP + kk * 16 + ac));
        ldsm4(aQi[kk], s2u(sh + 3 * TK + (wq0 + ar) * AP + kk * 16 + ac));
    }
    __syncthreads();   // frags extracted before buf1/P reused

    float m_[2] = {-1e30f, -1e30f}, l_[2] = {0.f, 0.f};
    float oAcc[8][4];
#pragma unroll
    for (int ni = 0; ni < 8; ni++)
#pragma unroll
        for (int cc = 0; cc < 4; cc++) oAcc[ni][cc] = 0.f;

    const int jt0 = (qx >= 1) ? (2 * qx - 2) : 0;

    stage_tile(jt0, sh);
    asm volatile("cp.async.wait_group 0;");
    __syncthreads();

    for (int jt = jt0; jt < LL / 64; jt++) {
        const int ib = (jt - jt0) & 1;
        const __half* cb = sh + ib * 3 * TK;

        if (jt + 1 < LL / 64)
            stage_tile(jt + 1, sh + (ib ^ 1) * 3 * TK);
        else
            asm volatile("cp.async.commit_group;");

        if (q0 + wq0 < jt * 64 + 192) {   // warp has unmasked keys this tile
            const __half* sKr = cb;
            const __half* sKi = cb + TK;
            const __half* sV  = cb + 2 * TK;

            float s[8][4];
#pragma unroll
            for (int ni = 0; ni < 8; ni++)
#pragma unroll
                for (int cc = 0; cc < 4; cc++) s[ni][cc] = 0.f;

#pragma unroll
            for (int kk = 0; kk < 4; kk++) {
#pragma unroll
                for (int np = 0; np < 4; np++) {
                    uint32_t bkr[4], bki[4];
                    ldsm4(bkr, s2u(sKr + (np * 16 + br) * AP + kk * 16 + bc));
                    ldsm4(bki, s2u(sKi + (np * 16 + br) * AP + kk * 16 + bc));
                    mma16(s[2*np],   aQr[kk], bkr[0], bkr[1]);
                    mma16(s[2*np+1], aQr[kk], bkr[2], bkr[3]);
                    mma16(s[2*np],   aQi[kk], bki[0], bki[1]);
                    mma16(s[2*np+1], aQi[kk], bki[2], bki[3]);
                }
            }

#pragma unroll
            for (int ni = 0; ni < 8; ni++)
#pragma unroll
                for (int cc = 0; cc < 4; cc++) s[ni][cc] *= 0.125f;

            if (q0 + wq0 + 15 >= jt * 64 + 129) {   // band mask can bite
                int ig0 = q0 + wq0 + (lane >> 2);
                int jg  = jt * 64 + ((lane & 3) << 1);
#pragma unroll
                for (int ni = 0; ni < 8; ni++) {
                    int j0 = jg + (ni << 3);
                    if (ig0 - j0     >= 129) s[ni][0] = -1e30f;
                    if (ig0 - j0 - 1 >= 129) s[ni][1] = -1e30f;
                    if (ig0 + 8 - j0 >= 129) s[ni][2] = -1e30f;
                    if (ig0 + 7 - j0 >= 129) s[ni][3] = -1e30f;
                }
            }

            float mx0 = -1e30f, mx1 = -1e30f;
#pragma unroll
            for (int ni = 0; ni < 8; ni++) {
                mx0 = fmaxf(mx0, fmaxf(s[ni][0], s[ni][1]));
                mx1 = fmaxf(mx1, fmaxf(s[ni][2], s[ni][3]));
            }
            mx0 = fmaxf(mx0, __shfl_xor_sync(0xffffffffu, mx0, 1));
            mx0 = fmaxf(mx0, __shfl_xor_sync(0xffffffffu, mx0, 2));
            mx1 = fmaxf(mx1, __shfl_xor_sync(0xffffffffu, mx1, 1));
            mx1 = fmaxf(mx1, __shfl_xor_sync(0xffffffffu, mx1, 2));

            float nm0 = fmaxf(m_[0], mx0), nm1 = fmaxf(m_[1], mx1);
            float corr0 = __expf(m_[0] - nm0), corr1 = __expf(m_[1] - nm1);
            m_[0] = nm0; m_[1] = nm1;

            float rs0 = 0.f, rs1 = 0.f;
#pragma unroll
            for (int ni = 0; ni < 8; ni++) {
                s[ni][0] = __expf(s[ni][0] - nm0); rs0 += s[ni][0];
                s[ni][1] = __expf(s[ni][1] - nm0); rs0 += s[ni][1];
                s[ni][2] = __expf(s[ni][2] - nm1); rs1 += s[ni][2];
                s[ni][3] = __expf(s[ni][3] - nm1); rs1 += s[ni][3];
            }
            rs0 += __shfl_xor_sync(0xffffffffu, rs0, 1);
            rs0 += __shfl_xor_sync(0xffffffffu, rs0, 2);
            rs1 += __shfl_xor_sync(0xffffffffu, rs1, 1);
            rs1 += __shfl_xor_sync(0xffffffffu, rs1, 2);

            l_[0] = l_[0] * corr0 + rs0;
            l_[1] = l_[1] * corr1 + rs1;
#pragma unroll
            for (int ni = 0; ni < 8; ni++) {
                oAcc[ni][0] *= corr0; oAcc[ni][1] *= corr0;
                oAcc[ni][2] *= corr1; oAcc[ni][3] *= corr1;
            }

            // ---- P -> smem fp16 (warp-private rows), PV ----
            {
                int r = wq0 + (lane >> 2);
                int c = (lane & 3) << 1;
                __half* sP = sh + SPPOF;
#pragma unroll
                for (int ni = 0; ni < 8; ni++) {
                    *(__half2*)&sP[r * AP + (ni << 3) + c] =
                        __floats2half2_rn(s[ni][0], s[ni][1]);
                    *(__half2*)&sP[(r + 8) * AP + (ni << 3) + c] =
                        __floats2half2_rn(s[ni][2], s[ni][3]);
                }
            }
            __syncwarp();

#pragma unroll
            for (int kk = 0; kk < 4; kk++) {
                uint32_t pa[4];
                ldsm4(pa, s2u(sh + SPPOF + (wq0 + ar) * AP + kk * 16 + ac));
#pragma unroll
                for (int dp = 0; dp < 4; dp++) {
                    uint32_t bv[4];
                    ldsm4(bv, s2u(sV + (dp * 16 + br) * AP + kk * 16 + bc));
                    mma16(oAcc[2*dp],   pa, bv[0], bv[1]);
                    mma16(oAcc[2*dp+1], pa, bv[2], bv[3]);
                }
            }
        }

        asm volatile("cp.async.wait_group 0;");
        __syncthreads();
    }

    // ---- epilogue: normalize, write fp16 [B,L,E] ----
    float inv0 = 1.f / l_[0], inv1 = 1.f / l_[1];
    int b_ = bh >> 3, h = bh & 7;
    int r  = q0 + wq0 + (lane >> 2);
    int c  = (lane & 3) << 1;
#pragma unroll
    for (int ni = 0; ni < 8; ni++) {
        int d = (ni << 3) + c;
        *(__half2*)(o + ((size_t)(b_ * LL + r)) * EE + h * DD + d) =
            __floats2half2_rn(oAcc[ni][0] * inv0, oAcc[ni][1] * inv0);
        *(__half2*)(o + ((size_t)(b_ * LL + r + 8)) * EE + h * DD + d) =
            __floats2half2_rn(oAcc[ni][2] * inv1, oAcc[ni][3] * inv1);
    }
}

// ---------------------------------------------------------------------------
extern "C" void kernel_launch(void* const* d_in, const int* in_sizes, int n_in,
                              void* d_out, int out_size)
{
    (void)in_sizes; (void)n_in; (void)out_size;
    const float* query = (const float*)d_in[0];
    const float* key_  = (const float*)d_in[1];
    const float* value = (const float*)d_in[2];
    const float* qWr = (const float*)d_in[3];
    const float* qWi = (const float*)d_in[4];
    const float* qbr = (const float*)d_in[5];
    const float* qbi = (const float*)d_in[6];
    const float* kWr = (const float*)d_in[7];
    const float* kWi = (const float*)d_in[8];
    const float* kbr = (const float*)d_in[9];
    const float* kbi = (const float*)d_in[10];
    const float* vWr = (const float*)d_in[11];
    const float* vbr = (const float*)d_in[13];
    // d_in[12] (vWi), d_in[14] (vbi) unused: Im(V) discarded by reference.
    const float* oWr = (const float*)d_in[15];
    const float* oWi = (const float*)d_in[16];
    const float* obr = (const float*)d_in[17];
    const float* obi = (const float*)d_in[18];
    float* out = (float*)d_out;

    __half *p_qr, *p_qi, *p_kr, *p_ki, *p_vr, *p_o;
    __half *p_q, *p_k, *p_v;
    __half *p_wqr, *p_wqi, *p_wkr, *p_wki, *p_wvr, *p_wor, *p_woi;
    cudaGetSymbolAddress((void**)&p_qr, g_qr);
    cudaGetSymbolAddress((void**)&p_qi, g_qi);
    cudaGetSymbolAddress((void**)&p_kr, g_kr);
    cudaGetSymbolAddress((void**)&p_ki, g_ki);
    cudaGetSymbolAddress((void**)&p_vr, g_vr);
    cudaGetSymbolAddress((void**)&p_o,  g_o);
    cudaGetSymbolAddress((void**)&p_q,  g_q);
    cudaGetSymbolAddress((void**)&p_k,  g_k);
    cudaGetSymbolAddress((void**)&p_v,  g_v);
    cudaGetSymbolAddress((void**)&p_wqr, g_wqr);
    cudaGetSymbolAddress((void**)&p_wqi, g_wqi);
    cudaGetSymbolAddress((void**)&p_wkr, g_wkr);
    cudaGetSymbolAddress((void**)&p_wki, g_wki);
    cudaGetSymbolAddress((void**)&p_wvr, g_wvr);
    cudaGetSymbolAddress((void**)&p_wor, g_wor);
    cudaGetSymbolAddress((void**)&p_woi, g_woi);

    cudaFuncSetAttribute(gemm_h,
                         cudaFuncAttributeMaxDynamicSharedMemorySize, GEMM_SMEM);
    cudaFuncSetAttribute(attn_h,
                         cudaFuncAttributeMaxDynamicSharedMemorySize, ATTN_SMEM);

    // ---- pre-convert inputs + live weights to fp16 ----
    {
        const int NI4 = MROWS * EE / 4;
        const int NW4 = EE * EE / 4;
        RTab rt;
        rt.t[0] = {query, p_q,   NI4};
        rt.t[1] = {key_,  p_k,   NI4};
        rt.t[2] = {value, p_v,   NI4};
        rt.t[3] = {qWr,   p_wqr, NW4};
        rt.t[4] = {qWi,   p_wqi, NW4};
        rt.t[5] = {kWr,   p_wkr, NW4};
        rt.t[6] = {kWi,   p_wki, NW4};
        rt.t[7] = {vWr,   p_wvr, NW4};
        rt.t[8] = {oWr,   p_wor, NW4};
        rt.t[9] = {oWi,   p_woi, NW4};
        conv_f16_k<<<dim3(1024, 10), 256>>>(rt);
    }

    dim3 ggrid5(EE / 128, MROWS / 128, 5);   // (4, 64, 5)
    dim3 ggrid2(EE / 128, MROWS / 128, 2);

    {
        GJobs pj;
        pj.j[0] = {p_q, p_wqr, qbr, p_qr, 1};
        pj.j[1] = {p_q, p_wqi, qbi, p_qi, 1};
        pj.j[2] = {p_k, p_wkr, kbr, p_kr, 1};
        pj.j[3] = {p_k, p_wki, kbi, p_ki, 1};
        pj.j[4] = {p_v, p_wvr, vbr, p_vr, 2};   // V transposed
        gemm_h<<<ggrid5, 256, GEMM_SMEM>>>(pj);
    }

    attn_h<<<dim3(BHD, LL / 128), 256, ATTN_SMEM>>>(p_qr, p_qi, p_kr, p_ki,
                                                    p_vr, p_o);

    {
        GJobs oj;
        oj.j[0] = {p_o, p_wor, obr, out, 0};
        oj.j[1] = {p_o, p_woi, obi, out + (size_t)MROWS * EE, 0};
        oj.j[2] = oj.j[0]; oj.j[3] = oj.j[0]; oj.j[4] = oj.j[0];
        gemm_h<<<ggrid2, 256, GEMM_SMEM>>>(oj);
    }
}